// round 9
// baseline (speedup 1.0000x reference)
#include <cuda_runtime.h>
#include <math.h>
#include <float.h>
#include <stdint.h>

#define NB    8
#define TLEN  4096
#define BT    (NB * TLEN)   // 32768
#define DM    128
#define HD    64
#define SK    68            // attn smem stride (f32)
#define CH    8             // kv tiles per chunk CTA

// Scratch (tf32-rounded bit patterns stored as float). Q pre-scaled by
// 1/sqrt(128)*log2(e) so attention scores are exp2-domain ready.
__device__ float g_Q[BT * HD];
__device__ float g_K[BT * HD];
__device__ float g_Vt[HD * BT];   // V transposed: [hd][b*T + t]

// Split-KV partials: per (qtile, chunk): unnormalized O (64x64), m, l (64)
__device__ float g_Po[NB * 64 * CH * 64 * 64];   // 67 MB
__device__ float g_Pm[NB * 64 * CH * 64];
__device__ float g_Pl[NB * 64 * CH * 64];

// ---------------------------------------------------------------------------
// helpers
// ---------------------------------------------------------------------------
__device__ __forceinline__ uint32_t f2tf32(float x) {
    uint32_t r;
    asm("cvt.rna.tf32.f32 %0, %1;" : "=r"(r) : "f"(x));
    return r;
}
__device__ __forceinline__ float tf32f(float x) {
    return __uint_as_float(f2tf32(x));
}
__device__ __forceinline__ float ex2f(float x) {
    float r;
    asm("ex2.approx.ftz.f32 %0, %1;" : "=f"(r) : "f"(x));
    return r;
}
__device__ __forceinline__ void mma_tf32(float* d, const uint32_t* a,
                                         uint32_t b0, uint32_t b1) {
    asm volatile(
        "mma.sync.aligned.m16n8k8.row.col.f32.tf32.tf32.f32 "
        "{%0,%1,%2,%3}, {%4,%5,%6,%7}, {%8,%9}, {%0,%1,%2,%3};\n"
        : "+f"(d[0]), "+f"(d[1]), "+f"(d[2]), "+f"(d[3])
        : "r"(a[0]), "r"(a[1]), "r"(a[2]), "r"(a[3]), "r"(b0), "r"(b1));
}
__device__ __forceinline__ void ldm_x4(uint32_t* r, const float* p) {
    uint32_t a = (uint32_t)__cvta_generic_to_shared(p);
    asm volatile("ldmatrix.sync.aligned.m8n8.x4.shared.b16 {%0,%1,%2,%3}, [%4];"
        : "=r"(r[0]), "=r"(r[1]), "=r"(r[2]), "=r"(r[3]) : "r"(a));
}
__device__ __forceinline__ void cpa16(float* dst, const float* src) {
    uint32_t d = (uint32_t)__cvta_generic_to_shared(dst);
    asm volatile("cp.async.cg.shared.global [%0], [%1], 16;" :: "r"(d), "l"(src));
}
#define CP_COMMIT() asm volatile("cp.async.commit_group;")
#define CP_WAIT0()  asm volatile("cp.async.wait_group 0;" ::: "memory")
#define CP_WAIT1()  asm volatile("cp.async.wait_group 1;" ::: "memory")

// softmax scale folded into Wq: 1/sqrt(128) * log2(e)
#define QSCL (0.08838834764831845f * 1.4426950408889634f)

// ---------------------------------------------------------------------------
// QKV projection, 256 threads = 8 warps. warp (rh=w>>1, wc=w&1):
// rows 16*rh..+15, cols 96*wc..+95. Per-warp regs ~110 -> 2 CTAs/SM,
// 16 warps/SM (vs ~7 before).
// ---------------------------------------------------------------------------
__global__ __launch_bounds__(256, 2) void qkv_kernel(
    const float* __restrict__ x,
    const float* __restrict__ Wq,
    const float* __restrict__ Wk,
    const float* __restrict__ Wv)
{
    extern __shared__ float sm[];
    float* Xs = sm;              // [64][132]

    const int tid  = threadIdx.x;
    const int row0 = blockIdx.x * 64;

    #pragma unroll
    for (int idx = tid; idx < 64 * 32; idx += 256) {
        int r = idx >> 5, c4 = idx & 31;
        float4 v = *(const float4*)(x + (size_t)(row0 + r) * DM + 4 * c4);
        v.x = tf32f(v.x); v.y = tf32f(v.y); v.z = tf32f(v.z); v.w = tf32f(v.w);
        *(float4*)&Xs[r * 132 + 4 * c4] = v;
    }
    __syncthreads();

    const int warp = tid >> 5, lane = tid & 31;
    const int g = lane >> 2, qi = lane & 3;
    const int rowbase = 16 * (warp >> 1);
    const int colbase = 96 * (warp & 1);
    const int arow = ((lane >> 3) & 1) * 8 + (lane & 7);
    const int acol = (lane >> 4) * 4;

    const float* wp[12];
    float wsc[12];
    #pragma unroll
    for (int nt = 0; nt < 12; nt++) {
        int c = colbase + 8 * nt + g;
        const float* Wb = (c < 64) ? Wq : ((c < 128) ? Wk : Wv);
        wp[nt] = Wb + (c & 63);
        wsc[nt] = (c < 64) ? QSCL : 1.0f;
    }

    float s[12][4];
    #pragma unroll
    for (int nt = 0; nt < 12; nt++)
        #pragma unroll
        for (int e = 0; e < 4; e++) s[nt][e] = 0.f;

    #pragma unroll
    for (int ks = 0; ks < 16; ks++) {
        uint32_t qa[4];
        ldm_x4(qa, &Xs[(rowbase + arow) * 132 + 8 * ks + acol]);
        int k0 = (8 * ks + qi) * 64, k1 = (8 * ks + qi + 4) * 64;
        #pragma unroll
        for (int nt = 0; nt < 12; nt++) {
            uint32_t b0 = f2tf32(__ldg(wp[nt] + k0) * wsc[nt]);
            uint32_t b1 = f2tf32(__ldg(wp[nt] + k1) * wsc[nt]);
            mma_tf32(s[nt], qa, b0, b1);
        }
    }

    #pragma unroll
    for (int nt = 0; nt < 12; nt++) {
        int c0 = colbase + 8 * nt + 2 * qi;
        int rA = row0 + rowbase + g;
        #pragma unroll
        for (int half = 0; half < 2; half++) {
            int r = rA + 8 * half;
            float v0 = tf32f(s[nt][2 * half + 0]);
            float v1 = tf32f(s[nt][2 * half + 1]);
            if (c0 < 64) {
                *(float2*)&g_Q[(size_t)r * HD + c0] = make_float2(v0, v1);
            } else if (c0 < 128) {
                *(float2*)&g_K[(size_t)r * HD + (c0 - 64)] = make_float2(v0, v1);
            } else {
                int h = c0 - 128;
                g_Vt[(size_t)h * BT + r]       = v0;
                g_Vt[(size_t)(h + 1) * BT + r] = v1;
            }
        }
    }
}

// ---------------------------------------------------------------------------
// Causal flash attention, split-KV (structure proven in R8).
// l is kept LANE-PARTIAL per iteration (exact: l'=l*a+rs is linear) and
// butterfly-reduced once in the epilogue -> 4 fewer serial SHFL per iter.
// ---------------------------------------------------------------------------
__global__ __launch_bounds__(128, 4) void attn_kernel(float* __restrict__ Out)
{
    extern __shared__ float sm[];
    float* Kb[2] = { sm, sm + 64 * SK };
    float* Vb = sm + 2 * 64 * SK;

    // map work unit -> (qb, chunk); biggest chunks scheduled first
    const int wu = 287 - (int)blockIdx.x;
    int gI = 0;
    while (wu >= 4 * (gI + 1) * (gI + 2)) gI++;       // offsets[g] = 4g(g+1)
    const int rem   = wu - 4 * gI * (gI + 1);
    const int qb    = 8 * gI + rem / (gI + 1);
    const int chunk = rem % (gI + 1);
    const int nch   = qb / CH + 1;                    // chunks for this qb
    const int t0 = chunk * CH;
    const int t1 = min(t0 + CH, qb + 1);

    const int b    = blockIdx.y;
    const int tid  = threadIdx.x;
    const int warp = tid >> 5, lane = tid & 31;
    const int g    = lane >> 2, qi = lane & 3;

    const int arow = ((lane >> 3) & 1) * 8 + (lane & 7);
    const int acol = (lane >> 4) * 4;
    const int brow = (lane & 7) + ((lane >> 4) << 3);
    const int bcol = ((lane >> 3) & 1) * 4;

    const float* Kg0 = g_K + (size_t)b * TLEN * HD;
    const float* Vg0 = g_Vt + (size_t)b * TLEN;

    // preload K(t0)+V(t0) as one group
    #pragma unroll
    for (int idx = tid; idx < 64 * 16; idx += 128) {
        int r = idx >> 4, c4 = (idx & 15) * 4;
        cpa16(&Kb[0][r * SK + c4], Kg0 + (size_t)(t0 * 64 + r) * HD + c4);
        cpa16(&Vb[r * SK + c4],    Vg0 + (size_t)r * BT + t0 * 64 + c4);
    }
    CP_COMMIT();

    // stage Q (pre-scaled tf32) into Kb[1], pull A-fragments
    const float* Qg = g_Q + ((size_t)b * TLEN + (size_t)qb * 64) * HD;
    #pragma unroll
    for (int idx = tid; idx < 64 * 16; idx += 128) {
        int r = idx >> 4, c4 = (idx & 15) * 4;
        *(float4*)&Kb[1][r * SK + c4] = *(const float4*)(Qg + (size_t)r * HD + c4);
    }
    __syncthreads();

    uint32_t qa[8][4];
    #pragma unroll
    for (int ks = 0; ks < 8; ks++)
        ldm_x4(qa[ks], &Kb[1][(16 * warp + arow) * SK + 8 * ks + acol]);

    float o[8][4];
    #pragma unroll
    for (int nt = 0; nt < 8; nt++)
        #pragma unroll
        for (int e = 0; e < 4; e++) o[nt][e] = 0.f;
    float m0 = -1e30f, m1 = -1e30f, l0 = 0.f, l1 = 0.f;  // l: lane-partial

    const int qr = 16 * warp + g;   // thread's first q-row (second is qr+8)

    for (int kb = t0; kb < t1; kb++) {
        const int cur = (kb - t0) & 1;

        CP_WAIT0();          // K(kb) (and V(t0) on first iter) landed
        __syncthreads();     // sync#1

        // group A: V(kb) (kb=t0 preloaded)
        if (kb > t0) {
            const float* Vg = Vg0 + (size_t)kb * 64;
            #pragma unroll
            for (int idx = tid; idx < 64 * 16; idx += 128) {
                int r = idx >> 4, c4 = (idx & 15) * 4;
                cpa16(&Vb[r * SK + c4], Vg + (size_t)r * BT + c4);
            }
        }
        CP_COMMIT();
        // group B: K(kb+1)
        if (kb + 1 < t1) {
            const float* Kg = Kg0 + (size_t)(kb + 1) * 64 * HD;
            #pragma unroll
            for (int idx = tid; idx < 64 * 16; idx += 128) {
                int r = idx >> 4, c4 = (idx & 15) * 4;
                cpa16(&Kb[1 - cur][r * SK + c4], Kg + (size_t)r * HD + c4);
            }
        }
        CP_COMMIT();

        // --- S = Q K^T (reads all 64 rows of Kb[cur]) ---
        float s[8][4];
        #pragma unroll
        for (int nt = 0; nt < 8; nt++)
            #pragma unroll
            for (int e = 0; e < 4; e++) s[nt][e] = 0.f;

        #pragma unroll
        for (int ks = 0; ks < 8; ks++) {
            #pragma unroll
            for (int ntp = 0; ntp < 4; ntp++) {
                uint32_t kf[4];
                ldm_x4(kf, &Kb[cur][(16 * ntp + brow) * SK + 8 * ks + bcol]);
                mma_tf32(s[2 * ntp],     qa[ks], kf[0], kf[1]);
                mma_tf32(s[2 * ntp + 1], qa[ks], kf[2], kf[3]);
            }
        }

        // --- causal mask: diagonal tile only ---
        if (kb == qb) {
            #pragma unroll
            for (int nt = 0; nt < 8; nt++) {
                int c0 = 8 * nt + 2 * qi;
                if (c0     > qr    ) s[nt][0] = -1e30f;
                if (c0 + 1 > qr    ) s[nt][1] = -1e30f;
                if (c0     > qr + 8) s[nt][2] = -1e30f;
                if (c0 + 1 > qr + 8) s[nt][3] = -1e30f;
            }
        }

        // --- online softmax (exp2 domain); m exact-reduced, l lane-partial ---
        float rm0 = -1e30f, rm1 = -1e30f;
        #pragma unroll
        for (int nt = 0; nt < 8; nt++) {
            rm0 = fmaxf(rm0, fmaxf(s[nt][0], s[nt][1]));
            rm1 = fmaxf(rm1, fmaxf(s[nt][2], s[nt][3]));
        }
        rm0 = fmaxf(rm0, __shfl_xor_sync(0xffffffffu, rm0, 1));
        rm0 = fmaxf(rm0, __shfl_xor_sync(0xffffffffu, rm0, 2));
        rm1 = fmaxf(rm1, __shfl_xor_sync(0xffffffffu, rm1, 1));
        rm1 = fmaxf(rm1, __shfl_xor_sync(0xffffffffu, rm1, 2));

        float mn0 = fmaxf(m0, rm0), mn1 = fmaxf(m1, rm1);
        float a0 = ex2f(m0 - mn0), a1 = ex2f(m1 - mn1);
        m0 = mn0; m1 = mn1;

        float rs0 = 0.f, rs1 = 0.f;
        #pragma unroll
        for (int nt = 0; nt < 8; nt++) {
            s[nt][0] = tf32f(ex2f(s[nt][0] - mn0));
            s[nt][1] = tf32f(ex2f(s[nt][1] - mn0));
            s[nt][2] = tf32f(ex2f(s[nt][2] - mn1));
            s[nt][3] = tf32f(ex2f(s[nt][3] - mn1));
            rs0 += s[nt][0] + s[nt][1];
            rs1 += s[nt][2] + s[nt][3];
        }
        l0 = l0 * a0 + rs0;   // lane-partial update (no shuffles)
        l1 = l1 * a1 + rs1;

        #pragma unroll
        for (int nt = 0; nt < 8; nt++) {
            o[nt][0] *= a0; o[nt][1] *= a0;
            o[nt][2] *= a1; o[nt][3] *= a1;
        }

        // V drain: last local iter has empty group B -> wait 0; else wait 1.
        if (kb + 1 < t1) { CP_WAIT1(); } else { CP_WAIT0(); }
        __syncthreads();   // sync#2: V visible AND all warps past QK reads

        // --- store P into dead K(cur) buffer (per-warp rows) ---
        #pragma unroll
        for (int nt = 0; nt < 8; nt++) {
            *(uint2*)&Kb[cur][qr * SK + 8 * nt + 2 * qi] =
                make_uint2(__float_as_uint(s[nt][0]), __float_as_uint(s[nt][1]));
            *(uint2*)&Kb[cur][(qr + 8) * SK + 8 * nt + 2 * qi] =
                make_uint2(__float_as_uint(s[nt][2]), __float_as_uint(s[nt][3]));
        }
        __syncwarp();

        // --- O += P V ---
        #pragma unroll
        for (int ks = 0; ks < 8; ks++) {
            uint32_t pa[4];
            ldm_x4(pa, &Kb[cur][(16 * warp + arow) * SK + 8 * ks + acol]);
            #pragma unroll
            for (int ntp = 0; ntp < 4; ntp++) {
                uint32_t vf[4];
                ldm_x4(vf, &Vb[(16 * ntp + brow) * SK + 8 * ks + bcol]);
                mma_tf32(o[2 * ntp],     pa, vf[0], vf[1]);
                mma_tf32(o[2 * ntp + 1], pa, vf[2], vf[3]);
            }
        }
    }

    // --- epilogue: reduce lane-partial l across the 4 qi lanes (exact) ---
    l0 += __shfl_xor_sync(0xffffffffu, l0, 1);
    l0 += __shfl_xor_sync(0xffffffffu, l0, 2);
    l1 += __shfl_xor_sync(0xffffffffu, l1, 1);
    l1 += __shfl_xor_sync(0xffffffffu, l1, 2);

    if (nch == 1) {
        // --- single chunk: finalize directly ---
        float* Og = Out + ((size_t)b * TLEN + (size_t)qb * 64) * HD;
        float i0 = 1.f / l0, i1 = 1.f / l1;
        #pragma unroll
        for (int nt = 0; nt < 8; nt++) {
            int c0 = 8 * nt + 2 * qi;
            *(float2*)&Og[(size_t)qr * HD + c0] =
                make_float2(o[nt][0] * i0, o[nt][1] * i0);
            *(float2*)&Og[(size_t)(qr + 8) * HD + c0] =
                make_float2(o[nt][2] * i1, o[nt][3] * i1);
        }
    } else {
        // --- write unnormalized partial + (m, l) ---
        const size_t pi = ((size_t)(b * 64 + qb) * CH + chunk);
        float* Po = g_Po + pi * 64 * 64;
        #pragma unroll
        for (int nt = 0; nt < 8; nt++) {
            int c0 = 8 * nt + 2 * qi;
            *(float2*)&Po[(size_t)qr * 64 + c0] =
                make_float2(o[nt][0], o[nt][1]);
            *(float2*)&Po[(size_t)(qr + 8) * 64 + c0] =
                make_float2(o[nt][2], o[nt][3]);
        }
        if (qi == 0) {
            g_Pm[pi * 64 + qr]     = m0;
            g_Pl[pi * 64 + qr]     = l0;
            g_Pm[pi * 64 + qr + 8] = m1;
            g_Pl[pi * 64 + qr + 8] = l1;
        }
    }
}

// ---------------------------------------------------------------------------
// Combine partials for qb >= CH. Grid (64-CH, NB), 256 threads.
// ---------------------------------------------------------------------------
__global__ __launch_bounds__(256) void combine_kernel(float* __restrict__ Out)
{
    const int qb  = CH + (int)blockIdx.x;     // 8..63
    const int b   = blockIdx.y;
    const int nch = qb / CH + 1;
    const int tid = threadIdx.x;
    const int row = tid >> 2;
    const int c0  = (tid & 3) * 16;
    const size_t qt = (size_t)(b * 64 + qb);

    float mv[CH], lv[CH];
    float mmax = -1e30f;
    for (int c = 0; c < nch; c++) {
        mv[c] = g_Pm[(qt * CH + c) * 64 + row];
        lv[c] = g_Pl[(qt * CH + c) * 64 + row];
        mmax = fmaxf(mmax, mv[c]);
    }
    float denom = 0.f;
    float w[CH];
    for (int c = 0; c < nch; c++) {
        w[c] = ex2f(mv[c] - mmax);
        denom += w[c] * lv[c];
    }
    const float inv = 1.f / denom;

    float4 acc[4];
    #pragma unroll
    for (int j = 0; j < 4; j++) acc[j] = make_float4(0.f, 0.f, 0.f, 0.f);

    for (int c = 0; c < nch; c++) {
        const float4* src = (const float4*)(g_Po +
            ((qt * CH + c) * 64 + row) * 64 + c0);
        float wc = w[c];
        #pragma unroll
        for (int j = 0; j < 4; j++) {
            float4 v = src[j];
            acc[j].x += wc * v.x; acc[j].y += wc * v.y;
            acc[j].z += wc * v.z; acc[j].w += wc * v.w;
        }
    }

    float4* dst = (float4*)(Out + ((size_t)b * TLEN + (size_t)qb * 64 + row) * HD + c0);
    #pragma unroll
    for (int j = 0; j < 4; j++) {
        dst[j] = make_float4(acc[j].x * inv, acc[j].y * inv,
                             acc[j].z * inv, acc[j].w * inv);
    }
}

// ---------------------------------------------------------------------------
extern "C" void kernel_launch(void* const* d_in, const int* in_sizes, int n_in,
                              void* d_out, int out_size)
{
    const float* x  = (const float*)d_in[0];
    const float* Wq = (const float*)d_in[1];
    const float* Wk = (const float*)d_in[2];
    const float* Wv = (const float*)d_in[3];
    float* out = (float*)d_out;

    const int smem_qkv  = 64 * 132 * (int)sizeof(float);      // 33792
    const int smem_attn = 3 * 64 * SK * (int)sizeof(float);   // 52224

    cudaFuncSetAttribute(qkv_kernel,
        cudaFuncAttributeMaxDynamicSharedMemorySize, smem_qkv);
    cudaFuncSetAttribute(attn_kernel,
        cudaFuncAttributeMaxDynamicSharedMemorySize, smem_attn);

    qkv_kernel<<<BT / 64, 256, smem_qkv>>>(x, Wq, Wk, Wv);
    attn_kernel<<<dim3(288, NB), 128, smem_attn>>>(out);
    combine_kernel<<<dim3(64 - CH, NB), 256>>>(out);
}

// round 10
// speedup vs baseline: 1.4445x; 1.4445x over previous
#include <cuda_runtime.h>
#include <cuda_fp16.h>
#include <math.h>
#include <float.h>
#include <stdint.h>

#define NB    8
#define TLEN  4096
#define BT    (NB * TLEN)   // 32768
#define DM    128
#define HD    64
#define SK    68            // K smem stride (f32)
#define VSK   72            // V smem stride (f16) -> conflict-free ldmatrix.trans
#define CH    8             // kv tiles per chunk CTA

// Scratch. Q pre-scaled by 1/sqrt(128)*log2(e); Q/K tf32-rounded f32; V fp16.
__device__ float  g_Q[BT * HD];
__device__ float  g_K[BT * HD];
__device__ __half g_Vh[BT * HD];   // natural [t][h], fp16

// Split-KV partials: per (qtile, chunk): unnormalized O (64x64), m, l (64)
__device__ float g_Po[NB * 64 * CH * 64 * 64];
__device__ float g_Pm[NB * 64 * CH * 64];
__device__ float g_Pl[NB * 64 * CH * 64];

// ---------------------------------------------------------------------------
// helpers
// ---------------------------------------------------------------------------
__device__ __forceinline__ uint32_t f2tf32(float x) {
    uint32_t r;
    asm("cvt.rna.tf32.f32 %0, %1;" : "=r"(r) : "f"(x));
    return r;
}
__device__ __forceinline__ float tf32f(float x) {
    return __uint_as_float(f2tf32(x));
}
__device__ __forceinline__ float ex2f(float x) {
    float r;
    asm("ex2.approx.ftz.f32 %0, %1;" : "=f"(r) : "f"(x));
    return r;
}
__device__ __forceinline__ uint32_t h2pack(float a, float b) {
    __half2 h = __floats2half2_rn(a, b);
    return *(uint32_t*)&h;
}
__device__ __forceinline__ void mma_tf32(float* d, const uint32_t* a,
                                         uint32_t b0, uint32_t b1) {
    asm volatile(
        "mma.sync.aligned.m16n8k8.row.col.f32.tf32.tf32.f32 "
        "{%0,%1,%2,%3}, {%4,%5,%6,%7}, {%8,%9}, {%0,%1,%2,%3};\n"
        : "+f"(d[0]), "+f"(d[1]), "+f"(d[2]), "+f"(d[3])
        : "r"(a[0]), "r"(a[1]), "r"(a[2]), "r"(a[3]), "r"(b0), "r"(b1));
}
__device__ __forceinline__ void mma_f16(float* d, const uint32_t* a,
                                        uint32_t b0, uint32_t b1) {
    asm volatile(
        "mma.sync.aligned.m16n8k16.row.col.f32.f16.f16.f32 "
        "{%0,%1,%2,%3}, {%4,%5,%6,%7}, {%8,%9}, {%0,%1,%2,%3};\n"
        : "+f"(d[0]), "+f"(d[1]), "+f"(d[2]), "+f"(d[3])
        : "r"(a[0]), "r"(a[1]), "r"(a[2]), "r"(a[3]), "r"(b0), "r"(b1));
}
__device__ __forceinline__ void ldm_x4(uint32_t* r, const float* p) {
    uint32_t a = (uint32_t)__cvta_generic_to_shared(p);
    asm volatile("ldmatrix.sync.aligned.m8n8.x4.shared.b16 {%0,%1,%2,%3}, [%4];"
        : "=r"(r[0]), "=r"(r[1]), "=r"(r[2]), "=r"(r[3]) : "r"(a));
}
__device__ __forceinline__ void ldm_x4t(uint32_t* r, const void* p) {
    uint32_t a = (uint32_t)__cvta_generic_to_shared(p);
    asm volatile("ldmatrix.sync.aligned.m8n8.x4.trans.shared.b16 {%0,%1,%2,%3}, [%4];"
        : "=r"(r[0]), "=r"(r[1]), "=r"(r[2]), "=r"(r[3]) : "r"(a));
}
__device__ __forceinline__ void cpa16(void* dst, const void* src) {
    uint32_t d = (uint32_t)__cvta_generic_to_shared(dst);
    asm volatile("cp.async.cg.shared.global [%0], [%1], 16;" :: "r"(d), "l"(src));
}
#define CP_COMMIT() asm volatile("cp.async.commit_group;")
#define CP_WAIT0()  asm volatile("cp.async.wait_group 0;" ::: "memory")

// softmax scale folded into Wq: 1/sqrt(128) * log2(e)
#define QSCL (0.08838834764831845f * 1.4426950408889634f)

// ---------------------------------------------------------------------------
// QKV projection, 128 thr = 4 warps (R8 structure). warp (rh=w>>1, wc=w&1):
// rows 32*rh..+31, cols 96*wc..+95. W streamed from global/L1.
// V written fp16 NATURAL [t][h] (coalesced half2 stores).
// ---------------------------------------------------------------------------
__global__ __launch_bounds__(128) void qkv_kernel(
    const float* __restrict__ x,
    const float* __restrict__ Wq,
    const float* __restrict__ Wk,
    const float* __restrict__ Wv)
{
    extern __shared__ float sm[];
    float* Xs = sm;              // [64][132]

    const int tid  = threadIdx.x;
    const int row0 = blockIdx.x * 64;

    #pragma unroll
    for (int idx = tid; idx < 64 * 32; idx += 128) {
        int r = idx >> 5, c4 = idx & 31;
        float4 v = *(const float4*)(x + (size_t)(row0 + r) * DM + 4 * c4);
        v.x = tf32f(v.x); v.y = tf32f(v.y); v.z = tf32f(v.z); v.w = tf32f(v.w);
        *(float4*)&Xs[r * 132 + 4 * c4] = v;
    }
    __syncthreads();

    const int warp = tid >> 5, lane = tid & 31;
    const int g = lane >> 2, qi = lane & 3;
    const int rowbase = 32 * (warp >> 1);
    const int colbase = 96 * (warp & 1);
    const int arow = ((lane >> 3) & 1) * 8 + (lane & 7);
    const int acol = (lane >> 4) * 4;

    const float* wp[12];
    float wsc[12];
    #pragma unroll
    for (int nt = 0; nt < 12; nt++) {
        int c = colbase + 8 * nt + g;
        const float* Wb = (c < 64) ? Wq : ((c < 128) ? Wk : Wv);
        wp[nt] = Wb + (c & 63);
        wsc[nt] = (c < 64) ? QSCL : 1.0f;
    }

    float s[2][12][4];
    #pragma unroll
    for (int rg = 0; rg < 2; rg++)
        #pragma unroll
        for (int nt = 0; nt < 12; nt++)
            #pragma unroll
            for (int e = 0; e < 4; e++) s[rg][nt][e] = 0.f;

    #pragma unroll
    for (int ks = 0; ks < 16; ks++) {
        uint32_t qa0[4], qa1[4];
        ldm_x4(qa0, &Xs[(rowbase + arow) * 132 + 8 * ks + acol]);
        ldm_x4(qa1, &Xs[(rowbase + 16 + arow) * 132 + 8 * ks + acol]);
        int k0 = (8 * ks + qi) * 64, k1 = (8 * ks + qi + 4) * 64;
        #pragma unroll
        for (int nt = 0; nt < 12; nt++) {
            uint32_t b0 = f2tf32(__ldg(wp[nt] + k0) * wsc[nt]);
            uint32_t b1 = f2tf32(__ldg(wp[nt] + k1) * wsc[nt]);
            mma_tf32(s[0][nt], qa0, b0, b1);
            mma_tf32(s[1][nt], qa1, b0, b1);
        }
    }

    #pragma unroll
    for (int rg = 0; rg < 2; rg++) {
        #pragma unroll
        for (int nt = 0; nt < 12; nt++) {
            int c0 = colbase + 8 * nt + 2 * qi;
            int rA = row0 + rowbase + 16 * rg + g;
            #pragma unroll
            for (int half = 0; half < 2; half++) {
                int r = rA + 8 * half;
                float v0 = s[rg][nt][2 * half + 0];
                float v1 = s[rg][nt][2 * half + 1];
                if (c0 < 64) {
                    *(float2*)&g_Q[(size_t)r * HD + c0] =
                        make_float2(tf32f(v0), tf32f(v1));
                } else if (c0 < 128) {
                    *(float2*)&g_K[(size_t)r * HD + (c0 - 64)] =
                        make_float2(tf32f(v0), tf32f(v1));
                } else {
                    int h = c0 - 128;
                    *(__half2*)&g_Vh[(size_t)r * HD + h] =
                        __floats2half2_rn(v0, v1);
                }
            }
        }
    }
}

// ---------------------------------------------------------------------------
// Causal flash attention, split-KV, fp16 PV.
// 128 thr = 4 warps, 16 q-rows/warp. K: tf32 double-buffer; V: fp16 double-
// buffer. P packed to fp16 A-fragments IN REGISTERS (accumulator layout ==
// m16n8k16 A layout pairwise) -> no P smem, ONE barrier per iteration.
// cp.async ledger: one group per iter = {K(kb+1), V(kb+1)}; at iter top the
// only outstanding group is (kb)'s -> CP_WAIT0.
// ---------------------------------------------------------------------------
__global__ __launch_bounds__(128, 4) void attn_kernel(float* __restrict__ Out)
{
    extern __shared__ float sm[];
    float*  Kb[2] = { sm, sm + 64 * SK };
    __half* Vh[2];
    Vh[0] = (__half*)(sm + 2 * 64 * SK);
    Vh[1] = Vh[0] + 64 * VSK;

    // map work unit -> (qb, chunk); biggest chunks scheduled first
    const int wu = 287 - (int)blockIdx.x;
    int gI = 0;
    while (wu >= 4 * (gI + 1) * (gI + 2)) gI++;       // offsets[g] = 4g(g+1)
    const int rem   = wu - 4 * gI * (gI + 1);
    const int qb    = 8 * gI + rem / (gI + 1);
    const int chunk = rem % (gI + 1);
    const int nch   = qb / CH + 1;
    const int t0 = chunk * CH;
    const int t1 = min(t0 + CH, qb + 1);

    const int b    = blockIdx.y;
    const int tid  = threadIdx.x;
    const int warp = tid >> 5, lane = tid & 31;
    const int g    = lane >> 2, qi = lane & 3;

    const int arow = ((lane >> 3) & 1) * 8 + (lane & 7);
    const int acol = (lane >> 4) * 4;
    const int brow = (lane & 7) + ((lane >> 4) << 3);
    const int bcol = ((lane >> 3) & 1) * 4;
    // V ldmatrix.trans lane pattern: row within 16-k block, 8-col group
    const int vrow  = ((lane >> 3) & 1) * 8 + (lane & 7);
    const int vcol8 = (lane >> 4) * 8;

    const float*  Kg0 = g_K + (size_t)b * TLEN * HD;
    const __half* Vg0 = g_Vh + (size_t)b * TLEN * HD;

    // preload K(t0)+V(t0) as one group
    #pragma unroll
    for (int idx = tid; idx < 64 * 16; idx += 128) {
        int r = idx >> 4, c4 = (idx & 15) * 4;
        cpa16(&Kb[0][r * SK + c4], Kg0 + (size_t)(t0 * 64 + r) * HD + c4);
    }
    #pragma unroll
    for (int idx = tid; idx < 64 * 8; idx += 128) {
        int r = idx >> 3, c8 = (idx & 7) * 8;
        cpa16(&Vh[0][r * VSK + c8], Vg0 + (size_t)(t0 * 64 + r) * HD + c8);
    }
    CP_COMMIT();

    // stage Q (pre-scaled tf32) into Kb[1], pull A-fragments
    const float* Qg = g_Q + ((size_t)b * TLEN + (size_t)qb * 64) * HD;
    #pragma unroll
    for (int idx = tid; idx < 64 * 16; idx += 128) {
        int r = idx >> 4, c4 = (idx & 15) * 4;
        *(float4*)&Kb[1][r * SK + c4] = *(const float4*)(Qg + (size_t)r * HD + c4);
    }
    __syncthreads();

    uint32_t qa[8][4];
    #pragma unroll
    for (int ks = 0; ks < 8; ks++)
        ldm_x4(qa[ks], &Kb[1][(16 * warp + arow) * SK + 8 * ks + acol]);

    float o[8][4];
    #pragma unroll
    for (int nt = 0; nt < 8; nt++)
        #pragma unroll
        for (int e = 0; e < 4; e++) o[nt][e] = 0.f;
    float m0 = -1e30f, m1 = -1e30f, l0 = 0.f, l1 = 0.f;  // l: lane-partial

    const int qr = 16 * warp + g;

    for (int kb = t0; kb < t1; kb++) {
        const int cur = (kb - t0) & 1;

        CP_WAIT0();          // K(kb), V(kb) landed
        __syncthreads();     // visible CTA-wide; prev readers of [1-cur] done

        // one prefetch group: K(kb+1) + V(kb+1) into [1-cur]
        if (kb + 1 < t1) {
            const float*  Kg = Kg0 + (size_t)(kb + 1) * 64 * HD;
            const __half* Vg = Vg0 + (size_t)(kb + 1) * 64 * HD;
            #pragma unroll
            for (int idx = tid; idx < 64 * 16; idx += 128) {
                int r = idx >> 4, c4 = (idx & 15) * 4;
                cpa16(&Kb[1 - cur][r * SK + c4], Kg + (size_t)r * HD + c4);
            }
            #pragma unroll
            for (int idx = tid; idx < 64 * 8; idx += 128) {
                int r = idx >> 3, c8 = (idx & 7) * 8;
                cpa16(&Vh[1 - cur][r * VSK + c8], Vg + (size_t)r * HD + c8);
            }
        }
        CP_COMMIT();

        // --- S = Q K^T ---
        float s[8][4];
        #pragma unroll
        for (int nt = 0; nt < 8; nt++)
            #pragma unroll
            for (int e = 0; e < 4; e++) s[nt][e] = 0.f;

        #pragma unroll
        for (int ks = 0; ks < 8; ks++) {
            #pragma unroll
            for (int ntp = 0; ntp < 4; ntp++) {
                uint32_t kf[4];
                ldm_x4(kf, &Kb[cur][(16 * ntp + brow) * SK + 8 * ks + bcol]);
                mma_tf32(s[2 * ntp],     qa[ks], kf[0], kf[1]);
                mma_tf32(s[2 * ntp + 1], qa[ks], kf[2], kf[3]);
            }
        }

        // --- causal mask: diagonal tile only ---
        if (kb == qb) {
            #pragma unroll
            for (int nt = 0; nt < 8; nt++) {
                int c0 = 8 * nt + 2 * qi;
                if (c0     > qr    ) s[nt][0] = -1e30f;
                if (c0 + 1 > qr    ) s[nt][1] = -1e30f;
                if (c0     > qr + 8) s[nt][2] = -1e30f;
                if (c0 + 1 > qr + 8) s[nt][3] = -1e30f;
            }
        }

        // --- online softmax (exp2 domain); l lane-partial ---
        float rm0 = -1e30f, rm1 = -1e30f;
        #pragma unroll
        for (int nt = 0; nt < 8; nt++) {
            rm0 = fmaxf(rm0, fmaxf(s[nt][0], s[nt][1]));
            rm1 = fmaxf(rm1, fmaxf(s[nt][2], s[nt][3]));
        }
        rm0 = fmaxf(rm0, __shfl_xor_sync(0xffffffffu, rm0, 1));
        rm0 = fmaxf(rm0, __shfl_xor_sync(0xffffffffu, rm0, 2));
        rm1 = fmaxf(rm1, __shfl_xor_sync(0xffffffffu, rm1, 1));
        rm1 = fmaxf(rm1, __shfl_xor_sync(0xffffffffu, rm1, 2));

        float mn0 = fmaxf(m0, rm0), mn1 = fmaxf(m1, rm1);
        float a0 = ex2f(m0 - mn0), a1 = ex2f(m1 - mn1);
        m0 = mn0; m1 = mn1;

        float rs0 = 0.f, rs1 = 0.f;
        #pragma unroll
        for (int nt = 0; nt < 8; nt++) {
            s[nt][0] = ex2f(s[nt][0] - mn0);
            s[nt][1] = ex2f(s[nt][1] - mn0);
            s[nt][2] = ex2f(s[nt][2] - mn1);
            s[nt][3] = ex2f(s[nt][3] - mn1);
            rs0 += s[nt][0] + s[nt][1];
            rs1 += s[nt][2] + s[nt][3];
        }
        l0 = l0 * a0 + rs0;
        l1 = l1 * a1 + rs1;

        #pragma unroll
        for (int nt = 0; nt < 8; nt++) {
            o[nt][0] *= a0; o[nt][1] *= a0;
            o[nt][2] *= a1; o[nt][3] *= a1;
        }

        // --- O += P V : P packed to fp16 A-frags in registers ---
        #pragma unroll
        for (int k4 = 0; k4 < 4; k4++) {
            uint32_t pa[4];
            pa[0] = h2pack(s[2 * k4][0],     s[2 * k4][1]);
            pa[1] = h2pack(s[2 * k4][2],     s[2 * k4][3]);
            pa[2] = h2pack(s[2 * k4 + 1][0], s[2 * k4 + 1][1]);
            pa[3] = h2pack(s[2 * k4 + 1][2], s[2 * k4 + 1][3]);
            #pragma unroll
            for (int np = 0; np < 4; np++) {
                uint32_t vf[4];
                ldm_x4t(vf, &Vh[cur][(16 * k4 + vrow) * VSK + 16 * np + vcol8]);
                mma_f16(o[2 * np],     pa, vf[0], vf[1]);
                mma_f16(o[2 * np + 1], pa, vf[2], vf[3]);
            }
        }
    }

    // --- epilogue: reduce lane-partial l across the 4 qi lanes (exact) ---
    l0 += __shfl_xor_sync(0xffffffffu, l0, 1);
    l0 += __shfl_xor_sync(0xffffffffu, l0, 2);
    l1 += __shfl_xor_sync(0xffffffffu, l1, 1);
    l1 += __shfl_xor_sync(0xffffffffu, l1, 2);

    if (nch == 1) {
        float* Og = Out + ((size_t)b * TLEN + (size_t)qb * 64) * HD;
        float i0 = 1.f / l0, i1 = 1.f / l1;
        #pragma unroll
        for (int nt = 0; nt < 8; nt++) {
            int c0 = 8 * nt + 2 * qi;
            *(float2*)&Og[(size_t)qr * HD + c0] =
                make_float2(o[nt][0] * i0, o[nt][1] * i0);
            *(float2*)&Og[(size_t)(qr + 8) * HD + c0] =
                make_float2(o[nt][2] * i1, o[nt][3] * i1);
        }
    } else {
        const size_t pi = ((size_t)(b * 64 + qb) * CH + chunk);
        float* Po = g_Po + pi * 64 * 64;
        #pragma unroll
        for (int nt = 0; nt < 8; nt++) {
            int c0 = 8 * nt + 2 * qi;
            *(float2*)&Po[(size_t)qr * 64 + c0] =
                make_float2(o[nt][0], o[nt][1]);
            *(float2*)&Po[(size_t)(qr + 8) * 64 + c0] =
                make_float2(o[nt][2], o[nt][3]);
        }
        if (qi == 0) {
            g_Pm[pi * 64 + qr]     = m0;
            g_Pl[pi * 64 + qr]     = l0;
            g_Pm[pi * 64 + qr + 8] = m1;
            g_Pl[pi * 64 + qr + 8] = l1;
        }
    }
}

// ---------------------------------------------------------------------------
// Combine partials for qb >= CH. Grid (64-CH, NB), 256 threads.
// ---------------------------------------------------------------------------
__global__ __launch_bounds__(256) void combine_kernel(float* __restrict__ Out)
{
    const int qb  = CH + (int)blockIdx.x;     // 8..63
    const int b   = blockIdx.y;
    const int nch = qb / CH + 1;
    const int tid = threadIdx.x;
    const int row = tid >> 2;
    const int c0  = (tid & 3) * 16;
    const size_t qt = (size_t)(b * 64 + qb);

    float mv[CH], lv[CH];
    float mmax = -1e30f;
    for (int c = 0; c < nch; c++) {
        mv[c] = g_Pm[(qt * CH + c) * 64 + row];
        lv[c] = g_Pl[(qt * CH + c) * 64 + row];
        mmax = fmaxf(mmax, mv[c]);
    }
    float denom = 0.f;
    float w[CH];
    for (int c = 0; c < nch; c++) {
        w[c] = ex2f(mv[c] - mmax);
        denom += w[c] * lv[c];
    }
    const float inv = 1.f / denom;

    float4 acc[4];
    #pragma unroll
    for (int j = 0; j < 4; j++) acc[j] = make_float4(0.f, 0.f, 0.f, 0.f);

    for (int c = 0; c < nch; c++) {
        const float4* src = (const float4*)(g_Po +
            ((qt * CH + c) * 64 + row) * 64 + c0);
        float wc = w[c];
        #pragma unroll
        for (int j = 0; j < 4; j++) {
            float4 v = src[j];
            acc[j].x += wc * v.x; acc[j].y += wc * v.y;
            acc[j].z += wc * v.z; acc[j].w += wc * v.w;
        }
    }

    float4* dst = (float4*)(Out + ((size_t)b * TLEN + (size_t)qb * 64 + row) * HD + c0);
    #pragma unroll
    for (int j = 0; j < 4; j++) {
        dst[j] = make_float4(acc[j].x * inv, acc[j].y * inv,
                             acc[j].z * inv, acc[j].w * inv);
    }
}

// ---------------------------------------------------------------------------
extern "C" void kernel_launch(void* const* d_in, const int* in_sizes, int n_in,
                              void* d_out, int out_size)
{
    const float* x  = (const float*)d_in[0];
    const float* Wq = (const float*)d_in[1];
    const float* Wk = (const float*)d_in[2];
    const float* Wv = (const float*)d_in[3];
    float* out = (float*)d_out;

    const int smem_qkv  = 64 * 132 * (int)sizeof(float);                 // 33792
    const int smem_attn = 2 * 64 * SK * (int)sizeof(float)
                        + 2 * 64 * VSK * (int)sizeof(__half);            // 53248

    cudaFuncSetAttribute(qkv_kernel,
        cudaFuncAttributeMaxDynamicSharedMemorySize, smem_qkv);
    cudaFuncSetAttribute(attn_kernel,
        cudaFuncAttributeMaxDynamicSharedMemorySize, smem_attn);

    qkv_kernel<<<BT / 64, 128, smem_qkv>>>(x, Wq, Wk, Wv);
    attn_kernel<<<dim3(288, NB), 128, smem_attn>>>(out);
    combine_kernel<<<dim3(64 - CH, NB), 256>>>(out);
}

// round 11
// speedup vs baseline: 1.8643x; 1.2906x over previous
#include <cuda_runtime.h>
#include <cuda_fp16.h>
#include <math.h>
#include <float.h>
#include <stdint.h>

#define NB    8
#define TLEN  4096
#define BT    (NB * TLEN)   // 32768
#define DM    128
#define HD    64
#define HSK   72            // half-precision smem stride (halves); 144B rows -> conflict-free ldmatrix
#define CH    8             // kv tiles per chunk CTA

// Scratch. Q pre-scaled by 1/sqrt(128)*log2(e). Q/K/V all fp16.
__device__ __half g_Qh[BT * HD];
__device__ __half g_Kh[BT * HD];
__device__ __half g_Vh[BT * HD];

// Split-KV partials: per (qtile, chunk): unnormalized O (64x64), m, l (64)
__device__ float g_Po[NB * 64 * CH * 64 * 64];
__device__ float g_Pm[NB * 64 * CH * 64];
__device__ float g_Pl[NB * 64 * CH * 64];

// ---------------------------------------------------------------------------
// helpers
// ---------------------------------------------------------------------------
__device__ __forceinline__ uint32_t f2tf32(float x) {
    uint32_t r;
    asm("cvt.rna.tf32.f32 %0, %1;" : "=r"(r) : "f"(x));
    return r;
}
__device__ __forceinline__ float tf32f(float x) {
    return __uint_as_float(f2tf32(x));
}
__device__ __forceinline__ float ex2f(float x) {
    float r;
    asm("ex2.approx.ftz.f32 %0, %1;" : "=f"(r) : "f"(x));
    return r;
}
__device__ __forceinline__ uint32_t h2pack(float a, float b) {
    __half2 h = __floats2half2_rn(a, b);
    return *(uint32_t*)&h;
}
__device__ __forceinline__ void mma_tf32(float* d, const uint32_t* a,
                                         uint32_t b0, uint32_t b1) {
    asm volatile(
        "mma.sync.aligned.m16n8k8.row.col.f32.tf32.tf32.f32 "
        "{%0,%1,%2,%3}, {%4,%5,%6,%7}, {%8,%9}, {%0,%1,%2,%3};\n"
        : "+f"(d[0]), "+f"(d[1]), "+f"(d[2]), "+f"(d[3])
        : "r"(a[0]), "r"(a[1]), "r"(a[2]), "r"(a[3]), "r"(b0), "r"(b1));
}
__device__ __forceinline__ void mma_f16(float* d, const uint32_t* a,
                                        uint32_t b0, uint32_t b1) {
    asm volatile(
        "mma.sync.aligned.m16n8k16.row.col.f32.f16.f16.f32 "
        "{%0,%1,%2,%3}, {%4,%5,%6,%7}, {%8,%9}, {%0,%1,%2,%3};\n"
        : "+f"(d[0]), "+f"(d[1]), "+f"(d[2]), "+f"(d[3])
        : "r"(a[0]), "r"(a[1]), "r"(a[2]), "r"(a[3]), "r"(b0), "r"(b1));
}
__device__ __forceinline__ void ldm_x4(uint32_t* r, const void* p) {
    uint32_t a = (uint32_t)__cvta_generic_to_shared(p);
    asm volatile("ldmatrix.sync.aligned.m8n8.x4.shared.b16 {%0,%1,%2,%3}, [%4];"
        : "=r"(r[0]), "=r"(r[1]), "=r"(r[2]), "=r"(r[3]) : "r"(a));
}
__device__ __forceinline__ void ldm_x4t(uint32_t* r, const void* p) {
    uint32_t a = (uint32_t)__cvta_generic_to_shared(p);
    asm volatile("ldmatrix.sync.aligned.m8n8.x4.trans.shared.b16 {%0,%1,%2,%3}, [%4];"
        : "=r"(r[0]), "=r"(r[1]), "=r"(r[2]), "=r"(r[3]) : "r"(a));
}
__device__ __forceinline__ void cpa16(void* dst, const void* src) {
    uint32_t d = (uint32_t)__cvta_generic_to_shared(dst);
    asm volatile("cp.async.cg.shared.global [%0], [%1], 16;" :: "r"(d), "l"(src));
}
#define CP_COMMIT() asm volatile("cp.async.commit_group;")
#define CP_WAIT0()  asm volatile("cp.async.wait_group 0;" ::: "memory")

// softmax scale folded into Wq: 1/sqrt(128) * log2(e)
#define QSCL (0.08838834764831845f * 1.4426950408889634f)

// ---------------------------------------------------------------------------
// QKV projection, 128 thr = 4 warps (R8 structure, tf32 mma on x/W).
// Outputs Q/K/V all fp16 (half2 coalesced stores); Q pre-scaled.
// ---------------------------------------------------------------------------
__global__ __launch_bounds__(128) void qkv_kernel(
    const float* __restrict__ x,
    const float* __restrict__ Wq,
    const float* __restrict__ Wk,
    const float* __restrict__ Wv)
{
    extern __shared__ float sm[];
    float* Xs = sm;              // [64][132]

    const int tid  = threadIdx.x;
    const int row0 = blockIdx.x * 64;

    #pragma unroll
    for (int idx = tid; idx < 64 * 32; idx += 128) {
        int r = idx >> 5, c4 = idx & 31;
        float4 v = *(const float4*)(x + (size_t)(row0 + r) * DM + 4 * c4);
        v.x = tf32f(v.x); v.y = tf32f(v.y); v.z = tf32f(v.z); v.w = tf32f(v.w);
        *(float4*)&Xs[r * 132 + 4 * c4] = v;
    }
    __syncthreads();

    const int warp = tid >> 5, lane = tid & 31;
    const int g = lane >> 2, qi = lane & 3;
    const int rowbase = 32 * (warp >> 1);
    const int colbase = 96 * (warp & 1);
    const int arow = ((lane >> 3) & 1) * 8 + (lane & 7);
    const int acol = (lane >> 4) * 4;

    const float* wp[12];
    float wsc[12];
    #pragma unroll
    for (int nt = 0; nt < 12; nt++) {
        int c = colbase + 8 * nt + g;
        const float* Wb = (c < 64) ? Wq : ((c < 128) ? Wk : Wv);
        wp[nt] = Wb + (c & 63);
        wsc[nt] = (c < 64) ? QSCL : 1.0f;
    }

    float s[2][12][4];
    #pragma unroll
    for (int rg = 0; rg < 2; rg++)
        #pragma unroll
        for (int nt = 0; nt < 12; nt++)
            #pragma unroll
            for (int e = 0; e < 4; e++) s[rg][nt][e] = 0.f;

    #pragma unroll
    for (int ks = 0; ks < 16; ks++) {
        uint32_t qa0[4], qa1[4];
        ldm_x4(qa0, &Xs[(rowbase + arow) * 132 + 8 * ks + acol]);
        ldm_x4(qa1, &Xs[(rowbase + 16 + arow) * 132 + 8 * ks + acol]);
        int k0 = (8 * ks + qi) * 64, k1 = (8 * ks + qi + 4) * 64;
        #pragma unroll
        for (int nt = 0; nt < 12; nt++) {
            uint32_t b0 = f2tf32(__ldg(wp[nt] + k0) * wsc[nt]);
            uint32_t b1 = f2tf32(__ldg(wp[nt] + k1) * wsc[nt]);
            mma_tf32(s[0][nt], qa0, b0, b1);
            mma_tf32(s[1][nt], qa1, b0, b1);
        }
    }

    #pragma unroll
    for (int rg = 0; rg < 2; rg++) {
        #pragma unroll
        for (int nt = 0; nt < 12; nt++) {
            int c0 = colbase + 8 * nt + 2 * qi;
            int rA = row0 + rowbase + 16 * rg + g;
            #pragma unroll
            for (int half = 0; half < 2; half++) {
                int r = rA + 8 * half;
                __half2 hv = __floats2half2_rn(s[rg][nt][2 * half + 0],
                                               s[rg][nt][2 * half + 1]);
                if (c0 < 64) {
                    *(__half2*)&g_Qh[(size_t)r * HD + c0] = hv;
                } else if (c0 < 128) {
                    *(__half2*)&g_Kh[(size_t)r * HD + (c0 - 64)] = hv;
                } else {
                    *(__half2*)&g_Vh[(size_t)r * HD + (c0 - 128)] = hv;
                }
            }
        }
    }
}

// ---------------------------------------------------------------------------
// Causal flash attention, split-KV, full fp16 tensor path (fp32 accum).
// 128 thr = 4 warps, 16 q-rows/warp. K/V fp16 double-buffered (36.9KB).
// QK: m16n8k16 (4 k-steps), K natural [n][k] read with non-trans ldmatrix.
// PV: m16n8k16, V natural [t][h] read with trans ldmatrix; P packed in regs.
// One cp.async group + ONE barrier per iteration.
// ---------------------------------------------------------------------------
__global__ __launch_bounds__(128, 4) void attn_kernel(float* __restrict__ Out)
{
    extern __shared__ float sm[];
    __half* base = (__half*)sm;
    __half* Kb[2] = { base,               base + 64 * HSK };
    __half* Vh[2] = { base + 2 * 64 * HSK, base + 3 * 64 * HSK };

    // map work unit -> (qb, chunk); biggest chunks scheduled first
    const int wu = 287 - (int)blockIdx.x;
    int gI = 0;
    while (wu >= 4 * (gI + 1) * (gI + 2)) gI++;       // offsets[g] = 4g(g+1)
    const int rem   = wu - 4 * gI * (gI + 1);
    const int qb    = 8 * gI + rem / (gI + 1);
    const int chunk = rem % (gI + 1);
    const int nch   = qb / CH + 1;
    const int t0 = chunk * CH;
    const int t1 = min(t0 + CH, qb + 1);

    const int b    = blockIdx.y;
    const int tid  = threadIdx.x;
    const int warp = tid >> 5, lane = tid & 31;
    const int g    = lane >> 2, qi = lane & 3;

    // fp16 ldmatrix lane patterns (stride HSK halves):
    const int arow  = ((lane >> 3) & 1) * 8 + (lane & 7);  // A: rows, col (lane>>4)*8
    const int acol8 = (lane >> 4) * 8;
    const int krow  = (lane & 7) + ((lane >> 4) << 3);     // K B: rows, col ((lane>>3)&1)*8
    const int kcol8 = ((lane >> 3) & 1) * 8;
    const int vrow  = ((lane >> 3) & 1) * 8 + (lane & 7);  // V B (trans)
    const int vcol8 = (lane >> 4) * 8;

    const __half* Kg0 = g_Kh + (size_t)b * TLEN * HD;
    const __half* Vg0 = g_Vh + (size_t)b * TLEN * HD;

    // preload K(t0)+V(t0) as one group (4 cpa16 each per thread)
    #pragma unroll
    for (int idx = tid; idx < 64 * 8; idx += 128) {
        int r = idx >> 3, c8 = (idx & 7) * 8;
        cpa16(&Kb[0][r * HSK + c8], Kg0 + (size_t)(t0 * 64 + r) * HD + c8);
        cpa16(&Vh[0][r * HSK + c8], Vg0 + (size_t)(t0 * 64 + r) * HD + c8);
    }
    CP_COMMIT();

    // stage Q (fp16, pre-scaled) into Kb[1], pull A-fragments
    const __half* Qg = g_Qh + ((size_t)b * TLEN + (size_t)qb * 64) * HD;
    #pragma unroll
    for (int idx = tid; idx < 64 * 8; idx += 128) {
        int r = idx >> 3, c8 = (idx & 7) * 8;
        *(uint4*)&Kb[1][r * HSK + c8] = *(const uint4*)(Qg + (size_t)r * HD + c8);
    }
    __syncthreads();

    uint32_t qa[4][4];
    #pragma unroll
    for (int ks = 0; ks < 4; ks++)
        ldm_x4(qa[ks], &Kb[1][(16 * warp + arow) * HSK + 16 * ks + acol8]);

    float o[8][4];
    #pragma unroll
    for (int nt = 0; nt < 8; nt++)
        #pragma unroll
        for (int e = 0; e < 4; e++) o[nt][e] = 0.f;
    float m0 = -1e30f, m1 = -1e30f, l0 = 0.f, l1 = 0.f;  // l: lane-partial

    const int qr = 16 * warp + g;

    for (int kb = t0; kb < t1; kb++) {
        const int cur = (kb - t0) & 1;

        CP_WAIT0();          // K(kb), V(kb) landed
        __syncthreads();     // visible CTA-wide; prev readers of [1-cur] done

        // one prefetch group: K(kb+1) + V(kb+1) into [1-cur]
        if (kb + 1 < t1) {
            const __half* Kg = Kg0 + (size_t)(kb + 1) * 64 * HD;
            const __half* Vg = Vg0 + (size_t)(kb + 1) * 64 * HD;
            #pragma unroll
            for (int idx = tid; idx < 64 * 8; idx += 128) {
                int r = idx >> 3, c8 = (idx & 7) * 8;
                cpa16(&Kb[1 - cur][r * HSK + c8], Kg + (size_t)r * HD + c8);
                cpa16(&Vh[1 - cur][r * HSK + c8], Vg + (size_t)r * HD + c8);
            }
        }
        CP_COMMIT();

        // --- S = Q K^T (fp16, 4 k-steps of 16) ---
        float s[8][4];
        #pragma unroll
        for (int nt = 0; nt < 8; nt++)
            #pragma unroll
            for (int e = 0; e < 4; e++) s[nt][e] = 0.f;

        #pragma unroll
        for (int ks = 0; ks < 4; ks++) {
            #pragma unroll
            for (int ntp = 0; ntp < 4; ntp++) {
                uint32_t kf[4];
                ldm_x4(kf, &Kb[cur][(16 * ntp + krow) * HSK + 16 * ks + kcol8]);
                mma_f16(s[2 * ntp],     qa[ks], kf[0], kf[1]);
                mma_f16(s[2 * ntp + 1], qa[ks], kf[2], kf[3]);
            }
        }

        // --- causal mask: diagonal tile only ---
        if (kb == qb) {
            #pragma unroll
            for (int nt = 0; nt < 8; nt++) {
                int c0 = 8 * nt + 2 * qi;
                if (c0     > qr    ) s[nt][0] = -1e30f;
                if (c0 + 1 > qr    ) s[nt][1] = -1e30f;
                if (c0     > qr + 8) s[nt][2] = -1e30f;
                if (c0 + 1 > qr + 8) s[nt][3] = -1e30f;
            }
        }

        // --- online softmax (exp2 domain); l lane-partial ---
        float rm0 = -1e30f, rm1 = -1e30f;
        #pragma unroll
        for (int nt = 0; nt < 8; nt++) {
            rm0 = fmaxf(rm0, fmaxf(s[nt][0], s[nt][1]));
            rm1 = fmaxf(rm1, fmaxf(s[nt][2], s[nt][3]));
        }
        rm0 = fmaxf(rm0, __shfl_xor_sync(0xffffffffu, rm0, 1));
        rm0 = fmaxf(rm0, __shfl_xor_sync(0xffffffffu, rm0, 2));
        rm1 = fmaxf(rm1, __shfl_xor_sync(0xffffffffu, rm1, 1));
        rm1 = fmaxf(rm1, __shfl_xor_sync(0xffffffffu, rm1, 2));

        float mn0 = fmaxf(m0, rm0), mn1 = fmaxf(m1, rm1);
        float a0 = ex2f(m0 - mn0), a1 = ex2f(m1 - mn1);
        m0 = mn0; m1 = mn1;

        float rs0 = 0.f, rs1 = 0.f;
        #pragma unroll
        for (int nt = 0; nt < 8; nt++) {
            s[nt][0] = ex2f(s[nt][0] - mn0);
            s[nt][1] = ex2f(s[nt][1] - mn0);
            s[nt][2] = ex2f(s[nt][2] - mn1);
            s[nt][3] = ex2f(s[nt][3] - mn1);
            rs0 += s[nt][0] + s[nt][1];
            rs1 += s[nt][2] + s[nt][3];
        }
        l0 = l0 * a0 + rs0;
        l1 = l1 * a1 + rs1;

        #pragma unroll
        for (int nt = 0; nt < 8; nt++) {
            o[nt][0] *= a0; o[nt][1] *= a0;
            o[nt][2] *= a1; o[nt][3] *= a1;
        }

        // --- O += P V : P packed to fp16 A-frags in registers ---
        #pragma unroll
        for (int k4 = 0; k4 < 4; k4++) {
            uint32_t pa[4];
            pa[0] = h2pack(s[2 * k4][0],     s[2 * k4][1]);
            pa[1] = h2pack(s[2 * k4][2],     s[2 * k4][3]);
            pa[2] = h2pack(s[2 * k4 + 1][0], s[2 * k4 + 1][1]);
            pa[3] = h2pack(s[2 * k4 + 1][2], s[2 * k4 + 1][3]);
            #pragma unroll
            for (int np = 0; np < 4; np++) {
                uint32_t vf[4];
                ldm_x4t(vf, &Vh[cur][(16 * k4 + vrow) * HSK + 16 * np + vcol8]);
                mma_f16(o[2 * np],     pa, vf[0], vf[1]);
                mma_f16(o[2 * np + 1], pa, vf[2], vf[3]);
            }
        }
    }

    // --- epilogue: reduce lane-partial l across the 4 qi lanes (exact) ---
    l0 += __shfl_xor_sync(0xffffffffu, l0, 1);
    l0 += __shfl_xor_sync(0xffffffffu, l0, 2);
    l1 += __shfl_xor_sync(0xffffffffu, l1, 1);
    l1 += __shfl_xor_sync(0xffffffffu, l1, 2);

    if (nch == 1) {
        float* Og = Out + ((size_t)b * TLEN + (size_t)qb * 64) * HD;
        float i0 = 1.f / l0, i1 = 1.f / l1;
        #pragma unroll
        for (int nt = 0; nt < 8; nt++) {
            int c0 = 8 * nt + 2 * qi;
            *(float2*)&Og[(size_t)qr * HD + c0] =
                make_float2(o[nt][0] * i0, o[nt][1] * i0);
            *(float2*)&Og[(size_t)(qr + 8) * HD + c0] =
                make_float2(o[nt][2] * i1, o[nt][3] * i1);
        }
    } else {
        const size_t pi = ((size_t)(b * 64 + qb) * CH + chunk);
        float* Po = g_Po + pi * 64 * 64;
        #pragma unroll
        for (int nt = 0; nt < 8; nt++) {
            int c0 = 8 * nt + 2 * qi;
            *(float2*)&Po[(size_t)qr * 64 + c0] =
                make_float2(o[nt][0], o[nt][1]);
            *(float2*)&Po[(size_t)(qr + 8) * 64 + c0] =
                make_float2(o[nt][2], o[nt][3]);
        }
        if (qi == 0) {
            g_Pm[pi * 64 + qr]     = m0;
            g_Pl[pi * 64 + qr]     = l0;
            g_Pm[pi * 64 + qr + 8] = m1;
            g_Pl[pi * 64 + qr + 8] = l1;
        }
    }
}

// ---------------------------------------------------------------------------
// Combine partials for qb >= CH. Grid (64-CH, NB), 256 threads.
// ---------------------------------------------------------------------------
__global__ __launch_bounds__(256) void combine_kernel(float* __restrict__ Out)
{
    const int qb  = CH + (int)blockIdx.x;     // 8..63
    const int b   = blockIdx.y;
    const int nch = qb / CH + 1;
    const int tid = threadIdx.x;
    const int row = tid >> 2;
    const int c0  = (tid & 3) * 16;
    const size_t qt = (size_t)(b * 64 + qb);

    float mv[CH], lv[CH];
    float mmax = -1e30f;
    for (int c = 0; c < nch; c++) {
        mv[c] = g_Pm[(qt * CH + c) * 64 + row];
        lv[c] = g_Pl[(qt * CH + c) * 64 + row];
        mmax = fmaxf(mmax, mv[c]);
    }
    float denom = 0.f;
    float w[CH];
    for (int c = 0; c < nch; c++) {
        w[c] = ex2f(mv[c] - mmax);
        denom += w[c] * lv[c];
    }
    const float inv = 1.f / denom;

    float4 acc[4];
    #pragma unroll
    for (int j = 0; j < 4; j++) acc[j] = make_float4(0.f, 0.f, 0.f, 0.f);

    for (int c = 0; c < nch; c++) {
        const float4* src = (const float4*)(g_Po +
            ((qt * CH + c) * 64 + row) * 64 + c0);
        float wc = w[c];
        #pragma unroll
        for (int j = 0; j < 4; j++) {
            float4 v = src[j];
            acc[j].x += wc * v.x; acc[j].y += wc * v.y;
            acc[j].z += wc * v.z; acc[j].w += wc * v.w;
        }
    }

    float4* dst = (float4*)(Out + ((size_t)b * TLEN + (size_t)qb * 64 + row) * HD + c0);
    #pragma unroll
    for (int j = 0; j < 4; j++) {
        dst[j] = make_float4(acc[j].x * inv, acc[j].y * inv,
                             acc[j].z * inv, acc[j].w * inv);
    }
}

// ---------------------------------------------------------------------------
extern "C" void kernel_launch(void* const* d_in, const int* in_sizes, int n_in,
                              void* d_out, int out_size)
{
    const float* x  = (const float*)d_in[0];
    const float* Wq = (const float*)d_in[1];
    const float* Wk = (const float*)d_in[2];
    const float* Wv = (const float*)d_in[3];
    float* out = (float*)d_out;

    const int smem_qkv  = 64 * 132 * (int)sizeof(float);              // 33792
    const int smem_attn = 4 * 64 * HSK * (int)sizeof(__half);         // 36864

    cudaFuncSetAttribute(qkv_kernel,
        cudaFuncAttributeMaxDynamicSharedMemorySize, smem_qkv);
    cudaFuncSetAttribute(attn_kernel,
        cudaFuncAttributeMaxDynamicSharedMemorySize, smem_attn);

    qkv_kernel<<<BT / 64, 128, smem_qkv>>>(x, Wq, Wk, Wv);
    attn_kernel<<<dim3(288, NB), 128, smem_attn>>>(out);
    combine_kernel<<<dim3(64 - CH, NB), 256>>>(out);
}

// round 12
// speedup vs baseline: 1.9872x; 1.0660x over previous
#include <cuda_runtime.h>
#include <cuda_fp16.h>
#include <math.h>
#include <float.h>
#include <stdint.h>

#define NB    8
#define TLEN  4096
#define BT    (NB * TLEN)   // 32768
#define DM    128
#define HD    64
#define HSK   72            // attn smem stride (halves); conflict-free ldmatrix
#define XSK   136           // qkv X smem stride (halves)
#define WSK   200           // qkv W smem stride (halves)
#define CH    8             // kv tiles per chunk CTA

// Scratch. Q pre-scaled by 1/sqrt(128)*log2(e). Q/K/V all fp16.
__device__ __half g_Qh[BT * HD];
__device__ __half g_Kh[BT * HD];
__device__ __half g_Vh[BT * HD];

// Split-KV partials: per (qtile, chunk): unnormalized O (64x64), m, l (64)
__device__ float g_Po[NB * 64 * CH * 64 * 64];
__device__ float g_Pm[NB * 64 * CH * 64];
__device__ float g_Pl[NB * 64 * CH * 64];

// ---------------------------------------------------------------------------
// helpers
// ---------------------------------------------------------------------------
__device__ __forceinline__ float ex2f(float x) {
    float r;
    asm("ex2.approx.ftz.f32 %0, %1;" : "=f"(r) : "f"(x));
    return r;
}
__device__ __forceinline__ uint32_t h2pack(float a, float b) {
    __half2 h = __floats2half2_rn(a, b);
    return *(uint32_t*)&h;
}
__device__ __forceinline__ void mma_f16(float* d, const uint32_t* a,
                                        uint32_t b0, uint32_t b1) {
    asm volatile(
        "mma.sync.aligned.m16n8k16.row.col.f32.f16.f16.f32 "
        "{%0,%1,%2,%3}, {%4,%5,%6,%7}, {%8,%9}, {%0,%1,%2,%3};\n"
        : "+f"(d[0]), "+f"(d[1]), "+f"(d[2]), "+f"(d[3])
        : "r"(a[0]), "r"(a[1]), "r"(a[2]), "r"(a[3]), "r"(b0), "r"(b1));
}
__device__ __forceinline__ void ldm_x4(uint32_t* r, const void* p) {
    uint32_t a = (uint32_t)__cvta_generic_to_shared(p);
    asm volatile("ldmatrix.sync.aligned.m8n8.x4.shared.b16 {%0,%1,%2,%3}, [%4];"
        : "=r"(r[0]), "=r"(r[1]), "=r"(r[2]), "=r"(r[3]) : "r"(a));
}
__device__ __forceinline__ void ldm_x4t(uint32_t* r, const void* p) {
    uint32_t a = (uint32_t)__cvta_generic_to_shared(p);
    asm volatile("ldmatrix.sync.aligned.m8n8.x4.trans.shared.b16 {%0,%1,%2,%3}, [%4];"
        : "=r"(r[0]), "=r"(r[1]), "=r"(r[2]), "=r"(r[3]) : "r"(a));
}
__device__ __forceinline__ void cpa16(void* dst, const void* src) {
    uint32_t d = (uint32_t)__cvta_generic_to_shared(dst);
    asm volatile("cp.async.cg.shared.global [%0], [%1], 16;" :: "r"(d), "l"(src));
}
#define CP_COMMIT() asm volatile("cp.async.commit_group;")
#define CP_WAIT0()  asm volatile("cp.async.wait_group 0;" ::: "memory")

// softmax scale folded into Wq: 1/sqrt(128) * log2(e)
#define QSCL (0.08838834764831845f * 1.4426950408889634f)

// ---------------------------------------------------------------------------
// QKV projection as an fp16 smem GEMM. CTA = 128 x-rows, 256 thr = 8 warps.
// warp (rg=w>>1, cg=w&1): rows 32*rg..+31, cols 96*cg..+95.
// X fp16 [128][XSK], W fp16 [128][WSK] staged ONCE (Wq pre-scaled by QSCL).
// A-frags: non-trans ldmatrix on X (attn Q pattern).
// B-frags: trans ldmatrix on natural [k][c] W (attn V pattern).
// ---------------------------------------------------------------------------
__global__ __launch_bounds__(256) void qkv_kernel(
    const float* __restrict__ x,
    const float* __restrict__ Wq,
    const float* __restrict__ Wk,
    const float* __restrict__ Wv)
{
    extern __shared__ __half smh[];
    __half* Xs = smh;               // [128][XSK]
    __half* Ws = smh + 128 * XSK;   // [128][WSK]

    const int tid  = threadIdx.x;
    const int row0 = blockIdx.x * 128;

    // stage X fp16 (128 rows x 128 k)
    #pragma unroll
    for (int idx = tid; idx < 128 * 32; idx += 256) {
        int r = idx >> 5, c4 = idx & 31;
        float4 v = *(const float4*)(x + (size_t)(row0 + r) * DM + 4 * c4);
        uint2 h;
        h.x = h2pack(v.x, v.y);
        h.y = h2pack(v.z, v.w);
        *(uint2*)&Xs[r * XSK + 4 * c4] = h;
    }
    // stage fused W fp16 (128 k x 192 c), Wq cols pre-scaled
    #pragma unroll
    for (int idx = tid; idx < 128 * 48; idx += 256) {
        int k = idx / 48, c4 = idx % 48;
        const float* src;
        float sc;
        if (c4 < 16)      { src = Wq + k * 64 + 4 * c4;        sc = QSCL; }
        else if (c4 < 32) { src = Wk + k * 64 + 4 * (c4 - 16); sc = 1.0f; }
        else              { src = Wv + k * 64 + 4 * (c4 - 32); sc = 1.0f; }
        float4 v = *(const float4*)src;
        uint2 h;
        h.x = h2pack(v.x * sc, v.y * sc);
        h.y = h2pack(v.z * sc, v.w * sc);
        *(uint2*)&Ws[k * WSK + 4 * c4] = h;
    }
    __syncthreads();

    const int warp = tid >> 5, lane = tid & 31;
    const int g = lane >> 2, qi = lane & 3;
    const int rowbase = 32 * (warp >> 1);
    const int colbase = 96 * (warp & 1);
    const int arow  = ((lane >> 3) & 1) * 8 + (lane & 7);
    const int acol8 = (lane >> 4) * 8;
    const int wrow  = ((lane >> 3) & 1) * 8 + (lane & 7);
    const int wcol8 = (lane >> 4) * 8;

    float s[2][12][4];
    #pragma unroll
    for (int rg = 0; rg < 2; rg++)
        #pragma unroll
        for (int nt = 0; nt < 12; nt++)
            #pragma unroll
            for (int e = 0; e < 4; e++) s[rg][nt][e] = 0.f;

    #pragma unroll
    for (int ks = 0; ks < 8; ks++) {
        uint32_t qa0[4], qa1[4];
        ldm_x4(qa0, &Xs[(rowbase + arow) * XSK + 16 * ks + acol8]);
        ldm_x4(qa1, &Xs[(rowbase + 16 + arow) * XSK + 16 * ks + acol8]);
        #pragma unroll
        for (int np = 0; np < 6; np++) {
            uint32_t wf[4];
            ldm_x4t(wf, &Ws[(16 * ks + wrow) * WSK + colbase + 16 * np + wcol8]);
            mma_f16(s[0][2 * np],     qa0, wf[0], wf[1]);
            mma_f16(s[1][2 * np],     qa1, wf[0], wf[1]);
            mma_f16(s[0][2 * np + 1], qa0, wf[2], wf[3]);
            mma_f16(s[1][2 * np + 1], qa1, wf[2], wf[3]);
        }
    }

    // scatter outputs fp16 (half2 coalesced)
    #pragma unroll
    for (int rg = 0; rg < 2; rg++) {
        #pragma unroll
        for (int nt = 0; nt < 12; nt++) {
            int c0 = colbase + 8 * nt + 2 * qi;
            int rA = row0 + rowbase + 16 * rg + g;
            #pragma unroll
            for (int half = 0; half < 2; half++) {
                int r = rA + 8 * half;
                __half2 hv = __floats2half2_rn(s[rg][nt][2 * half + 0],
                                               s[rg][nt][2 * half + 1]);
                if (c0 < 64) {
                    *(__half2*)&g_Qh[(size_t)r * HD + c0] = hv;
                } else if (c0 < 128) {
                    *(__half2*)&g_Kh[(size_t)r * HD + (c0 - 64)] = hv;
                } else {
                    *(__half2*)&g_Vh[(size_t)r * HD + (c0 - 128)] = hv;
                }
            }
        }
    }
}

// ---------------------------------------------------------------------------
// Causal flash attention, split-KV, full fp16 tensor path (fp32 accum).
// Unchanged from R11 (proven): 128 thr = 4 warps, 16 q-rows/warp,
// K/V fp16 double-buffered, one cp.async group + ONE barrier per iteration.
// ---------------------------------------------------------------------------
__global__ __launch_bounds__(128, 4) void attn_kernel(float* __restrict__ Out)
{
    extern __shared__ float sm[];
    __half* base = (__half*)sm;
    __half* Kb[2] = { base,                base + 64 * HSK };
    __half* Vh[2] = { base + 2 * 64 * HSK, base + 3 * 64 * HSK };

    // map work unit -> (qb, chunk); biggest chunks scheduled first
    const int wu = 287 - (int)blockIdx.x;
    int gI = 0;
    while (wu >= 4 * (gI + 1) * (gI + 2)) gI++;       // offsets[g] = 4g(g+1)
    const int rem   = wu - 4 * gI * (gI + 1);
    const int qb    = 8 * gI + rem / (gI + 1);
    const int chunk = rem % (gI + 1);
    const int nch   = qb / CH + 1;
    const int t0 = chunk * CH;
    const int t1 = min(t0 + CH, qb + 1);

    const int b    = blockIdx.y;
    const int tid  = threadIdx.x;
    const int warp = tid >> 5, lane = tid & 31;
    const int g    = lane >> 2, qi = lane & 3;

    const int arow  = ((lane >> 3) & 1) * 8 + (lane & 7);
    const int acol8 = (lane >> 4) * 8;
    const int krow  = (lane & 7) + ((lane >> 4) << 3);
    const int kcol8 = ((lane >> 3) & 1) * 8;
    const int vrow  = ((lane >> 3) & 1) * 8 + (lane & 7);
    const int vcol8 = (lane >> 4) * 8;

    const __half* Kg0 = g_Kh + (size_t)b * TLEN * HD;
    const __half* Vg0 = g_Vh + (size_t)b * TLEN * HD;

    // preload K(t0)+V(t0) as one group
    #pragma unroll
    for (int idx = tid; idx < 64 * 8; idx += 128) {
        int r = idx >> 3, c8 = (idx & 7) * 8;
        cpa16(&Kb[0][r * HSK + c8], Kg0 + (size_t)(t0 * 64 + r) * HD + c8);
        cpa16(&Vh[0][r * HSK + c8], Vg0 + (size_t)(t0 * 64 + r) * HD + c8);
    }
    CP_COMMIT();

    // stage Q (fp16, pre-scaled) into Kb[1], pull A-fragments
    const __half* Qg = g_Qh + ((size_t)b * TLEN + (size_t)qb * 64) * HD;
    #pragma unroll
    for (int idx = tid; idx < 64 * 8; idx += 128) {
        int r = idx >> 3, c8 = (idx & 7) * 8;
        *(uint4*)&Kb[1][r * HSK + c8] = *(const uint4*)(Qg + (size_t)r * HD + c8);
    }
    __syncthreads();

    uint32_t qa[4][4];
    #pragma unroll
    for (int ks = 0; ks < 4; ks++)
        ldm_x4(qa[ks], &Kb[1][(16 * warp + arow) * HSK + 16 * ks + acol8]);

    float o[8][4];
    #pragma unroll
    for (int nt = 0; nt < 8; nt++)
        #pragma unroll
        for (int e = 0; e < 4; e++) o[nt][e] = 0.f;
    float m0 = -1e30f, m1 = -1e30f, l0 = 0.f, l1 = 0.f;  // l: lane-partial

    const int qr = 16 * warp + g;

    for (int kb = t0; kb < t1; kb++) {
        const int cur = (kb - t0) & 1;

        CP_WAIT0();          // K(kb), V(kb) landed
        __syncthreads();     // visible CTA-wide; prev readers of [1-cur] done

        // one prefetch group: K(kb+1) + V(kb+1) into [1-cur]
        if (kb + 1 < t1) {
            const __half* Kg = Kg0 + (size_t)(kb + 1) * 64 * HD;
            const __half* Vg = Vg0 + (size_t)(kb + 1) * 64 * HD;
            #pragma unroll
            for (int idx = tid; idx < 64 * 8; idx += 128) {
                int r = idx >> 3, c8 = (idx & 7) * 8;
                cpa16(&Kb[1 - cur][r * HSK + c8], Kg + (size_t)r * HD + c8);
                cpa16(&Vh[1 - cur][r * HSK + c8], Vg + (size_t)r * HD + c8);
            }
        }
        CP_COMMIT();

        // --- S = Q K^T (fp16, 4 k-steps of 16) ---
        float s[8][4];
        #pragma unroll
        for (int nt = 0; nt < 8; nt++)
            #pragma unroll
            for (int e = 0; e < 4; e++) s[nt][e] = 0.f;

        #pragma unroll
        for (int ks = 0; ks < 4; ks++) {
            #pragma unroll
            for (int ntp = 0; ntp < 4; ntp++) {
                uint32_t kf[4];
                ldm_x4(kf, &Kb[cur][(16 * ntp + krow) * HSK + 16 * ks + kcol8]);
                mma_f16(s[2 * ntp],     qa[ks], kf[0], kf[1]);
                mma_f16(s[2 * ntp + 1], qa[ks], kf[2], kf[3]);
            }
        }

        // --- causal mask: diagonal tile only ---
        if (kb == qb) {
            #pragma unroll
            for (int nt = 0; nt < 8; nt++) {
                int c0 = 8 * nt + 2 * qi;
                if (c0     > qr    ) s[nt][0] = -1e30f;
                if (c0 + 1 > qr    ) s[nt][1] = -1e30f;
                if (c0     > qr + 8) s[nt][2] = -1e30f;
                if (c0 + 1 > qr + 8) s[nt][3] = -1e30f;
            }
        }

        // --- online softmax (exp2 domain); l lane-partial ---
        float rm0 = -1e30f, rm1 = -1e30f;
        #pragma unroll
        for (int nt = 0; nt < 8; nt++) {
            rm0 = fmaxf(rm0, fmaxf(s[nt][0], s[nt][1]));
            rm1 = fmaxf(rm1, fmaxf(s[nt][2], s[nt][3]));
        }
        rm0 = fmaxf(rm0, __shfl_xor_sync(0xffffffffu, rm0, 1));
        rm0 = fmaxf(rm0, __shfl_xor_sync(0xffffffffu, rm0, 2));
        rm1 = fmaxf(rm1, __shfl_xor_sync(0xffffffffu, rm1, 1));
        rm1 = fmaxf(rm1, __shfl_xor_sync(0xffffffffu, rm1, 2));

        float mn0 = fmaxf(m0, rm0), mn1 = fmaxf(m1, rm1);
        float a0 = ex2f(m0 - mn0), a1 = ex2f(m1 - mn1);
        m0 = mn0; m1 = mn1;

        float rs0 = 0.f, rs1 = 0.f;
        #pragma unroll
        for (int nt = 0; nt < 8; nt++) {
            s[nt][0] = ex2f(s[nt][0] - mn0);
            s[nt][1] = ex2f(s[nt][1] - mn0);
            s[nt][2] = ex2f(s[nt][2] - mn1);
            s[nt][3] = ex2f(s[nt][3] - mn1);
            rs0 += s[nt][0] + s[nt][1];
            rs1 += s[nt][2] + s[nt][3];
        }
        l0 = l0 * a0 + rs0;
        l1 = l1 * a1 + rs1;

        #pragma unroll
        for (int nt = 0; nt < 8; nt++) {
            o[nt][0] *= a0; o[nt][1] *= a0;
            o[nt][2] *= a1; o[nt][3] *= a1;
        }

        // --- O += P V : P packed to fp16 A-frags in registers ---
        #pragma unroll
        for (int k4 = 0; k4 < 4; k4++) {
            uint32_t pa[4];
            pa[0] = h2pack(s[2 * k4][0],     s[2 * k4][1]);
            pa[1] = h2pack(s[2 * k4][2],     s[2 * k4][3]);
            pa[2] = h2pack(s[2 * k4 + 1][0], s[2 * k4 + 1][1]);
            pa[3] = h2pack(s[2 * k4 + 1][2], s[2 * k4 + 1][3]);
            #pragma unroll
            for (int np = 0; np < 4; np++) {
                uint32_t vf[4];
                ldm_x4t(vf, &Vh[cur][(16 * k4 + vrow) * HSK + 16 * np + vcol8]);
                mma_f16(o[2 * np],     pa, vf[0], vf[1]);
                mma_f16(o[2 * np + 1], pa, vf[2], vf[3]);
            }
        }
    }

    // --- epilogue: reduce lane-partial l across the 4 qi lanes (exact) ---
    l0 += __shfl_xor_sync(0xffffffffu, l0, 1);
    l0 += __shfl_xor_sync(0xffffffffu, l0, 2);
    l1 += __shfl_xor_sync(0xffffffffu, l1, 1);
    l1 += __shfl_xor_sync(0xffffffffu, l1, 2);

    if (nch == 1) {
        float* Og = Out + ((size_t)b * TLEN + (size_t)qb * 64) * HD;
        float i0 = 1.f / l0, i1 = 1.f / l1;
        #pragma unroll
        for (int nt = 0; nt < 8; nt++) {
            int c0 = 8 * nt + 2 * qi;
            *(float2*)&Og[(size_t)qr * HD + c0] =
                make_float2(o[nt][0] * i0, o[nt][1] * i0);
            *(float2*)&Og[(size_t)(qr + 8) * HD + c0] =
                make_float2(o[nt][2] * i1, o[nt][3] * i1);
        }
    } else {
        const size_t pi = ((size_t)(b * 64 + qb) * CH + chunk);
        float* Po = g_Po + pi * 64 * 64;
        #pragma unroll
        for (int nt = 0; nt < 8; nt++) {
            int c0 = 8 * nt + 2 * qi;
            *(float2*)&Po[(size_t)qr * 64 + c0] =
                make_float2(o[nt][0], o[nt][1]);
            *(float2*)&Po[(size_t)(qr + 8) * 64 + c0] =
                make_float2(o[nt][2], o[nt][3]);
        }
        if (qi == 0) {
            g_Pm[pi * 64 + qr]     = m0;
            g_Pl[pi * 64 + qr]     = l0;
            g_Pm[pi * 64 + qr + 8] = m1;
            g_Pl[pi * 64 + qr + 8] = l1;
        }
    }
}

// ---------------------------------------------------------------------------
// Combine partials for qb >= CH. Grid (64-CH, NB), 256 threads.
// ---------------------------------------------------------------------------
__global__ __launch_bounds__(256) void combine_kernel(float* __restrict__ Out)
{
    const int qb  = CH + (int)blockIdx.x;     // 8..63
    const int b   = blockIdx.y;
    const int nch = qb / CH + 1;
    const int tid = threadIdx.x;
    const int row = tid >> 2;
    const int c0  = (tid & 3) * 16;
    const size_t qt = (size_t)(b * 64 + qb);

    float mv[CH], lv[CH];
    float mmax = -1e30f;
    for (int c = 0; c < nch; c++) {
        mv[c] = g_Pm[(qt * CH + c) * 64 + row];
        lv[c] = g_Pl[(qt * CH + c) * 64 + row];
        mmax = fmaxf(mmax, mv[c]);
    }
    float denom = 0.f;
    float w[CH];
    for (int c = 0; c < nch; c++) {
        w[c] = ex2f(mv[c] - mmax);
        denom += w[c] * lv[c];
    }
    const float inv = 1.f / denom;

    float4 acc[4];
    #pragma unroll
    for (int j = 0; j < 4; j++) acc[j] = make_float4(0.f, 0.f, 0.f, 0.f);

    for (int c = 0; c < nch; c++) {
        const float4* src = (const float4*)(g_Po +
            ((qt * CH + c) * 64 + row) * 64 + c0);
        float wc = w[c];
        #pragma unroll
        for (int j = 0; j < 4; j++) {
            float4 v = src[j];
            acc[j].x += wc * v.x; acc[j].y += wc * v.y;
            acc[j].z += wc * v.z; acc[j].w += wc * v.w;
        }
    }

    float4* dst = (float4*)(Out + ((size_t)b * TLEN + (size_t)qb * 64 + row) * HD + c0);
    #pragma unroll
    for (int j = 0; j < 4; j++) {
        dst[j] = make_float4(acc[j].x * inv, acc[j].y * inv,
                             acc[j].z * inv, acc[j].w * inv);
    }
}

// ---------------------------------------------------------------------------
extern "C" void kernel_launch(void* const* d_in, const int* in_sizes, int n_in,
                              void* d_out, int out_size)
{
    const float* x  = (const float*)d_in[0];
    const float* Wq = (const float*)d_in[1];
    const float* Wk = (const float*)d_in[2];
    const float* Wv = (const float*)d_in[3];
    float* out = (float*)d_out;

    const int smem_qkv  = (128 * XSK + 128 * WSK) * (int)sizeof(__half); // 86016
    const int smem_attn = 4 * 64 * HSK * (int)sizeof(__half);            // 36864

    cudaFuncSetAttribute(qkv_kernel,
        cudaFuncAttributeMaxDynamicSharedMemorySize, smem_qkv);
    cudaFuncSetAttribute(attn_kernel,
        cudaFuncAttributeMaxDynamicSharedMemorySize, smem_attn);

    qkv_kernel<<<BT / 128, 256, smem_qkv>>>(x, Wq, Wk, Wv);
    attn_kernel<<<dim3(288, NB), 128, smem_attn>>>(out);
    combine_kernel<<<dim3(64 - CH, NB), 256>>>(out);
}

// round 13
// speedup vs baseline: 2.0343x; 1.0237x over previous
#include <cuda_runtime.h>
#include <cuda_fp16.h>
#include <math.h>
#include <float.h>
#include <stdint.h>

#define NB    8
#define TLEN  4096
#define BT    (NB * TLEN)   // 32768
#define DM    128
#define HD    64
#define HSK   72            // attn smem stride (halves); conflict-free ldmatrix
#define XSK   136           // qkv X smem stride (halves)
#define WSK   200           // qkv W smem stride (halves)
#define CH    8             // kv tiles per chunk CTA

// Scratch. Q pre-scaled by 1/sqrt(128)*log2(e). Everything fp16.
__device__ __half g_Xh[BT * DM];        // x converted to fp16
__device__ __half g_Wh[DM * 192];       // fused W fp16 [k][Q|K|V], Wq pre-scaled
__device__ __half g_Qh[BT * HD];
__device__ __half g_Kh[BT * HD];
__device__ __half g_Vh[BT * HD];

// Split-KV partials: per (qtile, chunk): unnormalized O (64x64), m, l (64)
__device__ float g_Po[NB * 64 * CH * 64 * 64];
__device__ float g_Pm[NB * 64 * CH * 64];
__device__ float g_Pl[NB * 64 * CH * 64];

// ---------------------------------------------------------------------------
// helpers
// ---------------------------------------------------------------------------
__device__ __forceinline__ float ex2f(float x) {
    float r;
    asm("ex2.approx.ftz.f32 %0, %1;" : "=f"(r) : "f"(x));
    return r;
}
__device__ __forceinline__ uint32_t h2pack(float a, float b) {
    __half2 h = __floats2half2_rn(a, b);
    return *(uint32_t*)&h;
}
__device__ __forceinline__ void mma_f16(float* d, const uint32_t* a,
                                        uint32_t b0, uint32_t b1) {
    asm volatile(
        "mma.sync.aligned.m16n8k16.row.col.f32.f16.f16.f32 "
        "{%0,%1,%2,%3}, {%4,%5,%6,%7}, {%8,%9}, {%0,%1,%2,%3};\n"
        : "+f"(d[0]), "+f"(d[1]), "+f"(d[2]), "+f"(d[3])
        : "r"(a[0]), "r"(a[1]), "r"(a[2]), "r"(a[3]), "r"(b0), "r"(b1));
}
__device__ __forceinline__ void ldm_x4(uint32_t* r, const void* p) {
    uint32_t a = (uint32_t)__cvta_generic_to_shared(p);
    asm volatile("ldmatrix.sync.aligned.m8n8.x4.shared.b16 {%0,%1,%2,%3}, [%4];"
        : "=r"(r[0]), "=r"(r[1]), "=r"(r[2]), "=r"(r[3]) : "r"(a));
}
__device__ __forceinline__ void ldm_x4t(uint32_t* r, const void* p) {
    uint32_t a = (uint32_t)__cvta_generic_to_shared(p);
    asm volatile("ldmatrix.sync.aligned.m8n8.x4.trans.shared.b16 {%0,%1,%2,%3}, [%4];"
        : "=r"(r[0]), "=r"(r[1]), "=r"(r[2]), "=r"(r[3]) : "r"(a));
}
__device__ __forceinline__ void cpa16(void* dst, const void* src) {
    uint32_t d = (uint32_t)__cvta_generic_to_shared(dst);
    asm volatile("cp.async.cg.shared.global [%0], [%1], 16;" :: "r"(d), "l"(src));
}
#define CP_COMMIT() asm volatile("cp.async.commit_group;")
#define CP_WAIT0()  asm volatile("cp.async.wait_group 0;" ::: "memory")

// softmax scale folded into Wq: 1/sqrt(128) * log2(e)
#define QSCL (0.08838834764831845f * 1.4426950408889634f)

// ---------------------------------------------------------------------------
// Streaming conversion: x fp32 -> g_Xh fp16; W -> fused pre-scaled g_Wh.
// Pure bandwidth kernel, high occupancy.
// ---------------------------------------------------------------------------
__global__ __launch_bounds__(256) void cvt_kernel(
    const float* __restrict__ x,
    const float* __restrict__ Wq,
    const float* __restrict__ Wk,
    const float* __restrict__ Wv)
{
    const int tid = blockIdx.x * 256 + threadIdx.x;
    // x: BT*DM = 4.19M elems = 1,048,576 float4
    const int NX4 = BT * DM / 4;
    for (int i = tid; i < NX4; i += (int)gridDim.x * 256) {
        float4 v = *(const float4*)(x + 4 * (size_t)i);
        uint2 h;
        h.x = h2pack(v.x, v.y);
        h.y = h2pack(v.z, v.w);
        *(uint2*)&g_Xh[4 * (size_t)i] = h;
    }
    // W: 128 k-rows x 192 cols = 6144 float4-quads
    const int NW4 = DM * 192 / 4;
    for (int i = tid; i < NW4; i += (int)gridDim.x * 256) {
        int k  = (4 * i) / 192;
        int c  = (4 * i) % 192;
        const float* src;
        float sc;
        if (c < 64)       { src = Wq + k * 64 + c;        sc = QSCL; }
        else if (c < 128) { src = Wk + k * 64 + (c - 64); sc = 1.0f; }
        else              { src = Wv + k * 64 + (c - 128); sc = 1.0f; }
        float4 v = *(const float4*)src;
        uint2 h;
        h.x = h2pack(v.x * sc, v.y * sc);
        h.y = h2pack(v.z * sc, v.w * sc);
        *(uint2*)&g_Wh[k * 192 + c] = h;
    }
}

// ---------------------------------------------------------------------------
// QKV projection as an fp16 smem GEMM, cp.async staging only.
// CTA = 128 x-rows, 256 thr = 8 warps; warp (rg=w>>1, cg=w&1).
// ---------------------------------------------------------------------------
__global__ __launch_bounds__(256) void qkv_kernel()
{
    extern __shared__ __half smh[];
    __half* Xs = smh;               // [128][XSK]
    __half* Ws = smh + 128 * XSK;   // [128][WSK]

    const int tid  = threadIdx.x;
    const int row0 = blockIdx.x * 128;

    // stage X fp16: 128 rows x 16 chunks of 8 halves
    #pragma unroll
    for (int idx = tid; idx < 128 * 16; idx += 256) {
        int r = idx >> 4, c8 = (idx & 15) * 8;
        cpa16(&Xs[r * XSK + c8], g_Xh + (size_t)(row0 + r) * DM + c8);
    }
    // stage W fp16: 128 k-rows x 24 chunks of 8 halves
    #pragma unroll
    for (int idx = tid; idx < 128 * 24; idx += 256) {
        int k = idx / 24, c8 = (idx % 24) * 8;
        cpa16(&Ws[k * WSK + c8], g_Wh + k * 192 + c8);
    }
    CP_COMMIT();
    CP_WAIT0();
    __syncthreads();

    const int warp = tid >> 5, lane = tid & 31;
    const int g = lane >> 2, qi = lane & 3;
    const int rowbase = 32 * (warp >> 1);
    const int colbase = 96 * (warp & 1);
    const int arow  = ((lane >> 3) & 1) * 8 + (lane & 7);
    const int acol8 = (lane >> 4) * 8;
    const int wrow  = ((lane >> 3) & 1) * 8 + (lane & 7);
    const int wcol8 = (lane >> 4) * 8;

    float s[2][12][4];
    #pragma unroll
    for (int rg = 0; rg < 2; rg++)
        #pragma unroll
        for (int nt = 0; nt < 12; nt++)
            #pragma unroll
            for (int e = 0; e < 4; e++) s[rg][nt][e] = 0.f;

    #pragma unroll
    for (int ks = 0; ks < 8; ks++) {
        uint32_t qa0[4], qa1[4];
        ldm_x4(qa0, &Xs[(rowbase + arow) * XSK + 16 * ks + acol8]);
        ldm_x4(qa1, &Xs[(rowbase + 16 + arow) * XSK + 16 * ks + acol8]);
        #pragma unroll
        for (int np = 0; np < 6; np++) {
            uint32_t wf[4];
            ldm_x4t(wf, &Ws[(16 * ks + wrow) * WSK + colbase + 16 * np + wcol8]);
            mma_f16(s[0][2 * np],     qa0, wf[0], wf[1]);
            mma_f16(s[1][2 * np],     qa1, wf[0], wf[1]);
            mma_f16(s[0][2 * np + 1], qa0, wf[2], wf[3]);
            mma_f16(s[1][2 * np + 1], qa1, wf[2], wf[3]);
        }
    }

    // scatter outputs fp16 (half2 coalesced)
    #pragma unroll
    for (int rg = 0; rg < 2; rg++) {
        #pragma unroll
        for (int nt = 0; nt < 12; nt++) {
            int c0 = colbase + 8 * nt + 2 * qi;
            int rA = row0 + rowbase + 16 * rg + g;
            #pragma unroll
            for (int half = 0; half < 2; half++) {
                int r = rA + 8 * half;
                __half2 hv = __floats2half2_rn(s[rg][nt][2 * half + 0],
                                               s[rg][nt][2 * half + 1]);
                if (c0 < 64) {
                    *(__half2*)&g_Qh[(size_t)r * HD + c0] = hv;
                } else if (c0 < 128) {
                    *(__half2*)&g_Kh[(size_t)r * HD + (c0 - 64)] = hv;
                } else {
                    *(__half2*)&g_Vh[(size_t)r * HD + (c0 - 128)] = hv;
                }
            }
        }
    }
}

// ---------------------------------------------------------------------------
// Causal flash attention, split-KV, full fp16 tensor path (fp32 accum).
// Unchanged from R11/R12 (proven).
// ---------------------------------------------------------------------------
__global__ __launch_bounds__(128, 4) void attn_kernel(float* __restrict__ Out)
{
    extern __shared__ float sm[];
    __half* base = (__half*)sm;
    __half* Kb[2] = { base,                base + 64 * HSK };
    __half* Vh[2] = { base + 2 * 64 * HSK, base + 3 * 64 * HSK };

    // map work unit -> (qb, chunk); biggest chunks scheduled first
    const int wu = 287 - (int)blockIdx.x;
    int gI = 0;
    while (wu >= 4 * (gI + 1) * (gI + 2)) gI++;       // offsets[g] = 4g(g+1)
    const int rem   = wu - 4 * gI * (gI + 1);
    const int qb    = 8 * gI + rem / (gI + 1);
    const int chunk = rem % (gI + 1);
    const int nch   = qb / CH + 1;
    const int t0 = chunk * CH;
    const int t1 = min(t0 + CH, qb + 1);

    const int b    = blockIdx.y;
    const int tid  = threadIdx.x;
    const int warp = tid >> 5, lane = tid & 31;
    const int g    = lane >> 2, qi = lane & 3;

    const int arow  = ((lane >> 3) & 1) * 8 + (lane & 7);
    const int acol8 = (lane >> 4) * 8;
    const int krow  = (lane & 7) + ((lane >> 4) << 3);
    const int kcol8 = ((lane >> 3) & 1) * 8;
    const int vrow  = ((lane >> 3) & 1) * 8 + (lane & 7);
    const int vcol8 = (lane >> 4) * 8;

    const __half* Kg0 = g_Kh + (size_t)b * TLEN * HD;
    const __half* Vg0 = g_Vh + (size_t)b * TLEN * HD;

    // preload K(t0)+V(t0) as one group
    #pragma unroll
    for (int idx = tid; idx < 64 * 8; idx += 128) {
        int r = idx >> 3, c8 = (idx & 7) * 8;
        cpa16(&Kb[0][r * HSK + c8], Kg0 + (size_t)(t0 * 64 + r) * HD + c8);
        cpa16(&Vh[0][r * HSK + c8], Vg0 + (size_t)(t0 * 64 + r) * HD + c8);
    }
    CP_COMMIT();

    // stage Q (fp16, pre-scaled) into Kb[1], pull A-fragments
    const __half* Qg = g_Qh + ((size_t)b * TLEN + (size_t)qb * 64) * HD;
    #pragma unroll
    for (int idx = tid; idx < 64 * 8; idx += 128) {
        int r = idx >> 3, c8 = (idx & 7) * 8;
        *(uint4*)&Kb[1][r * HSK + c8] = *(const uint4*)(Qg + (size_t)r * HD + c8);
    }
    __syncthreads();

    uint32_t qa[4][4];
    #pragma unroll
    for (int ks = 0; ks < 4; ks++)
        ldm_x4(qa[ks], &Kb[1][(16 * warp + arow) * HSK + 16 * ks + acol8]);

    float o[8][4];
    #pragma unroll
    for (int nt = 0; nt < 8; nt++)
        #pragma unroll
        for (int e = 0; e < 4; e++) o[nt][e] = 0.f;
    float m0 = -1e30f, m1 = -1e30f, l0 = 0.f, l1 = 0.f;  // l: lane-partial

    const int qr = 16 * warp + g;

    for (int kb = t0; kb < t1; kb++) {
        const int cur = (kb - t0) & 1;

        CP_WAIT0();          // K(kb), V(kb) landed
        __syncthreads();     // visible CTA-wide; prev readers of [1-cur] done

        // one prefetch group: K(kb+1) + V(kb+1) into [1-cur]
        if (kb + 1 < t1) {
            const __half* Kg = Kg0 + (size_t)(kb + 1) * 64 * HD;
            const __half* Vg = Vg0 + (size_t)(kb + 1) * 64 * HD;
            #pragma unroll
            for (int idx = tid; idx < 64 * 8; idx += 128) {
                int r = idx >> 3, c8 = (idx & 7) * 8;
                cpa16(&Kb[1 - cur][r * HSK + c8], Kg + (size_t)r * HD + c8);
                cpa16(&Vh[1 - cur][r * HSK + c8], Vg + (size_t)r * HD + c8);
            }
        }
        CP_COMMIT();

        // --- S = Q K^T (fp16, 4 k-steps of 16) ---
        float s[8][4];
        #pragma unroll
        for (int nt = 0; nt < 8; nt++)
            #pragma unroll
            for (int e = 0; e < 4; e++) s[nt][e] = 0.f;

        #pragma unroll
        for (int ks = 0; ks < 4; ks++) {
            #pragma unroll
            for (int ntp = 0; ntp < 4; ntp++) {
                uint32_t kf[4];
                ldm_x4(kf, &Kb[cur][(16 * ntp + krow) * HSK + 16 * ks + kcol8]);
                mma_f16(s[2 * ntp],     qa[ks], kf[0], kf[1]);
                mma_f16(s[2 * ntp + 1], qa[ks], kf[2], kf[3]);
            }
        }

        // --- causal mask: diagonal tile only ---
        if (kb == qb) {
            #pragma unroll
            for (int nt = 0; nt < 8; nt++) {
                int c0 = 8 * nt + 2 * qi;
                if (c0     > qr    ) s[nt][0] = -1e30f;
                if (c0 + 1 > qr    ) s[nt][1] = -1e30f;
                if (c0     > qr + 8) s[nt][2] = -1e30f;
                if (c0 + 1 > qr + 8) s[nt][3] = -1e30f;
            }
        }

        // --- online softmax (exp2 domain); l lane-partial ---
        float rm0 = -1e30f, rm1 = -1e30f;
        #pragma unroll
        for (int nt = 0; nt < 8; nt++) {
            rm0 = fmaxf(rm0, fmaxf(s[nt][0], s[nt][1]));
            rm1 = fmaxf(rm1, fmaxf(s[nt][2], s[nt][3]));
        }
        rm0 = fmaxf(rm0, __shfl_xor_sync(0xffffffffu, rm0, 1));
        rm0 = fmaxf(rm0, __shfl_xor_sync(0xffffffffu, rm0, 2));
        rm1 = fmaxf(rm1, __shfl_xor_sync(0xffffffffu, rm1, 1));
        rm1 = fmaxf(rm1, __shfl_xor_sync(0xffffffffu, rm1, 2));

        float mn0 = fmaxf(m0, rm0), mn1 = fmaxf(m1, rm1);
        float a0 = ex2f(m0 - mn0), a1 = ex2f(m1 - mn1);
        m0 = mn0; m1 = mn1;

        float rs0 = 0.f, rs1 = 0.f;
        #pragma unroll
        for (int nt = 0; nt < 8; nt++) {
            s[nt][0] = ex2f(s[nt][0] - mn0);
            s[nt][1] = ex2f(s[nt][1] - mn0);
            s[nt][2] = ex2f(s[nt][2] - mn1);
            s[nt][3] = ex2f(s[nt][3] - mn1);
            rs0 += s[nt][0] + s[nt][1];
            rs1 += s[nt][2] + s[nt][3];
        }
        l0 = l0 * a0 + rs0;
        l1 = l1 * a1 + rs1;

        #pragma unroll
        for (int nt = 0; nt < 8; nt++) {
            o[nt][0] *= a0; o[nt][1] *= a0;
            o[nt][2] *= a1; o[nt][3] *= a1;
        }

        // --- O += P V : P packed to fp16 A-frags in registers ---
        #pragma unroll
        for (int k4 = 0; k4 < 4; k4++) {
            uint32_t pa[4];
            pa[0] = h2pack(s[2 * k4][0],     s[2 * k4][1]);
            pa[1] = h2pack(s[2 * k4][2],     s[2 * k4][3]);
            pa[2] = h2pack(s[2 * k4 + 1][0], s[2 * k4 + 1][1]);
            pa[3] = h2pack(s[2 * k4 + 1][2], s[2 * k4 + 1][3]);
            #pragma unroll
            for (int np = 0; np < 4; np++) {
                uint32_t vf[4];
                ldm_x4t(vf, &Vh[cur][(16 * k4 + vrow) * HSK + 16 * np + vcol8]);
                mma_f16(o[2 * np],     pa, vf[0], vf[1]);
                mma_f16(o[2 * np + 1], pa, vf[2], vf[3]);
            }
        }
    }

    // --- epilogue: reduce lane-partial l across the 4 qi lanes (exact) ---
    l0 += __shfl_xor_sync(0xffffffffu, l0, 1);
    l0 += __shfl_xor_sync(0xffffffffu, l0, 2);
    l1 += __shfl_xor_sync(0xffffffffu, l1, 1);
    l1 += __shfl_xor_sync(0xffffffffu, l1, 2);

    if (nch == 1) {
        float* Og = Out + ((size_t)b * TLEN + (size_t)qb * 64) * HD;
        float i0 = 1.f / l0, i1 = 1.f / l1;
        #pragma unroll
        for (int nt = 0; nt < 8; nt++) {
            int c0 = 8 * nt + 2 * qi;
            *(float2*)&Og[(size_t)qr * HD + c0] =
                make_float2(o[nt][0] * i0, o[nt][1] * i0);
            *(float2*)&Og[(size_t)(qr + 8) * HD + c0] =
                make_float2(o[nt][2] * i1, o[nt][3] * i1);
        }
    } else {
        const size_t pi = ((size_t)(b * 64 + qb) * CH + chunk);
        float* Po = g_Po + pi * 64 * 64;
        #pragma unroll
        for (int nt = 0; nt < 8; nt++) {
            int c0 = 8 * nt + 2 * qi;
            *(float2*)&Po[(size_t)qr * 64 + c0] =
                make_float2(o[nt][0], o[nt][1]);
            *(float2*)&Po[(size_t)(qr + 8) * 64 + c0] =
                make_float2(o[nt][2], o[nt][3]);
        }
        if (qi == 0) {
            g_Pm[pi * 64 + qr]     = m0;
            g_Pl[pi * 64 + qr]     = l0;
            g_Pm[pi * 64 + qr + 8] = m1;
            g_Pl[pi * 64 + qr + 8] = l1;
        }
    }
}

// ---------------------------------------------------------------------------
// Combine partials for qb >= CH. Grid (64-CH, NB), 256 threads.
// ---------------------------------------------------------------------------
__global__ __launch_bounds__(256) void combine_kernel(float* __restrict__ Out)
{
    const int qb  = CH + (int)blockIdx.x;     // 8..63
    const int b   = blockIdx.y;
    const int nch = qb / CH + 1;
    const int tid = threadIdx.x;
    const int row = tid >> 2;
    const int c0  = (tid & 3) * 16;
    const size_t qt = (size_t)(b * 64 + qb);

    float mv[CH], lv[CH];
    float mmax = -1e30f;
    for (int c = 0; c < nch; c++) {
        mv[c] = g_Pm[(qt * CH + c) * 64 + row];
        lv[c] = g_Pl[(qt * CH + c) * 64 + row];
        mmax = fmaxf(mmax, mv[c]);
    }
    float denom = 0.f;
    float w[CH];
    for (int c = 0; c < nch; c++) {
        w[c] = ex2f(mv[c] - mmax);
        denom += w[c] * lv[c];
    }
    const float inv = 1.f / denom;

    float4 acc[4];
    #pragma unroll
    for (int j = 0; j < 4; j++) acc[j] = make_float4(0.f, 0.f, 0.f, 0.f);

    for (int c = 0; c < nch; c++) {
        const float4* src = (const float4*)(g_Po +
            ((qt * CH + c) * 64 + row) * 64 + c0);
        float wc = w[c];
        #pragma unroll
        for (int j = 0; j < 4; j++) {
            float4 v = src[j];
            acc[j].x += wc * v.x; acc[j].y += wc * v.y;
            acc[j].z += wc * v.z; acc[j].w += wc * v.w;
        }
    }

    float4* dst = (float4*)(Out + ((size_t)b * TLEN + (size_t)qb * 64 + row) * HD + c0);
    #pragma unroll
    for (int j = 0; j < 4; j++) {
        dst[j] = make_float4(acc[j].x * inv, acc[j].y * inv,
                             acc[j].z * inv, acc[j].w * inv);
    }
}

// ---------------------------------------------------------------------------
extern "C" void kernel_launch(void* const* d_in, const int* in_sizes, int n_in,
                              void* d_out, int out_size)
{
    const float* x  = (const float*)d_in[0];
    const float* Wq = (const float*)d_in[1];
    const float* Wk = (const float*)d_in[2];
    const float* Wv = (const float*)d_in[3];
    float* out = (float*)d_out;

    const int smem_qkv  = (128 * XSK + 128 * WSK) * (int)sizeof(__half); // 86016
    const int smem_attn = 4 * 64 * HSK * (int)sizeof(__half);            // 36864

    cudaFuncSetAttribute(qkv_kernel,
        cudaFuncAttributeMaxDynamicSharedMemorySize, smem_qkv);
    cudaFuncSetAttribute(attn_kernel,
        cudaFuncAttributeMaxDynamicSharedMemorySize, smem_attn);

    cvt_kernel<<<1184, 256>>>(x, Wq, Wk, Wv);
    qkv_kernel<<<BT / 128, 256, smem_qkv>>>();
    attn_kernel<<<dim3(288, NB), 128, smem_attn>>>(out);
    combine_kernel<<<dim3(64 - CH, NB), 256>>>(out);
}

// round 14
// speedup vs baseline: 2.0897x; 1.0272x over previous
#include <cuda_runtime.h>
#include <cuda_fp16.h>
#include <math.h>
#include <float.h>
#include <stdint.h>

#define NB    8
#define TLEN  4096
#define BT    (NB * TLEN)   // 32768
#define DM    128
#define HD    64
#define HSK   72            // attn smem stride (halves); conflict-free ldmatrix
#define XSK   136           // qkv X smem stride (halves)
#define WSK   200           // qkv W smem stride (halves)
#define CH    16            // kv tiles per chunk CTA
#define MAXNCH 4            // max chunks per q-tile (64/CH)

// Scratch. Q pre-scaled by 1/sqrt(128)*log2(e). Everything fp16.
__device__ __half g_Xh[BT * DM];        // x converted to fp16
__device__ __half g_Wh[DM * 192];       // fused W fp16 [k][Q|K|V], Wq pre-scaled
__device__ __half g_Qh[BT * HD];
__device__ __half g_Kh[BT * HD];
__device__ __half g_Vh[BT * HD];

// Split-KV partials: per (qtile, chunk): unnormalized O (64x64), m, l (64)
__device__ float g_Po[NB * 64 * MAXNCH * 64 * 64];   // 33.5 MB
__device__ float g_Pm[NB * 64 * MAXNCH * 64];
__device__ float g_Pl[NB * 64 * MAXNCH * 64];

// ---------------------------------------------------------------------------
// helpers
// ---------------------------------------------------------------------------
__device__ __forceinline__ float ex2f(float x) {
    float r;
    asm("ex2.approx.ftz.f32 %0, %1;" : "=f"(r) : "f"(x));
    return r;
}
__device__ __forceinline__ uint32_t h2pack(float a, float b) {
    __half2 h = __floats2half2_rn(a, b);
    return *(uint32_t*)&h;
}
__device__ __forceinline__ void mma_f16(float* d, const uint32_t* a,
                                        uint32_t b0, uint32_t b1) {
    asm volatile(
        "mma.sync.aligned.m16n8k16.row.col.f32.f16.f16.f32 "
        "{%0,%1,%2,%3}, {%4,%5,%6,%7}, {%8,%9}, {%0,%1,%2,%3};\n"
        : "+f"(d[0]), "+f"(d[1]), "+f"(d[2]), "+f"(d[3])
        : "r"(a[0]), "r"(a[1]), "r"(a[2]), "r"(a[3]), "r"(b0), "r"(b1));
}
__device__ __forceinline__ void ldm_x4(uint32_t* r, const void* p) {
    uint32_t a = (uint32_t)__cvta_generic_to_shared(p);
    asm volatile("ldmatrix.sync.aligned.m8n8.x4.shared.b16 {%0,%1,%2,%3}, [%4];"
        : "=r"(r[0]), "=r"(r[1]), "=r"(r[2]), "=r"(r[3]) : "r"(a));
}
__device__ __forceinline__ void ldm_x4t(uint32_t* r, const void* p) {
    uint32_t a = (uint32_t)__cvta_generic_to_shared(p);
    asm volatile("ldmatrix.sync.aligned.m8n8.x4.trans.shared.b16 {%0,%1,%2,%3}, [%4];"
        : "=r"(r[0]), "=r"(r[1]), "=r"(r[2]), "=r"(r[3]) : "r"(a));
}
__device__ __forceinline__ void cpa16(void* dst, const void* src) {
    uint32_t d = (uint32_t)__cvta_generic_to_shared(dst);
    asm volatile("cp.async.cg.shared.global [%0], [%1], 16;" :: "r"(d), "l"(src));
}
#define CP_COMMIT() asm volatile("cp.async.commit_group;")
#define CP_WAIT0()  asm volatile("cp.async.wait_group 0;" ::: "memory")

// softmax scale folded into Wq: 1/sqrt(128) * log2(e)
#define QSCL (0.08838834764831845f * 1.4426950408889634f)

// ---------------------------------------------------------------------------
// Streaming conversion: x fp32 -> g_Xh fp16; W -> fused pre-scaled g_Wh.
// ---------------------------------------------------------------------------
__global__ __launch_bounds__(256) void cvt_kernel(
    const float* __restrict__ x,
    const float* __restrict__ Wq,
    const float* __restrict__ Wk,
    const float* __restrict__ Wv)
{
    const int tid = blockIdx.x * 256 + threadIdx.x;
    const int NX4 = BT * DM / 4;
    for (int i = tid; i < NX4; i += (int)gridDim.x * 256) {
        float4 v = *(const float4*)(x + 4 * (size_t)i);
        uint2 h;
        h.x = h2pack(v.x, v.y);
        h.y = h2pack(v.z, v.w);
        *(uint2*)&g_Xh[4 * (size_t)i] = h;
    }
    const int NW4 = DM * 192 / 4;
    for (int i = tid; i < NW4; i += (int)gridDim.x * 256) {
        int k  = (4 * i) / 192;
        int c  = (4 * i) % 192;
        const float* src;
        float sc;
        if (c < 64)       { src = Wq + k * 64 + c;        sc = QSCL; }
        else if (c < 128) { src = Wk + k * 64 + (c - 64); sc = 1.0f; }
        else              { src = Wv + k * 64 + (c - 128); sc = 1.0f; }
        float4 v = *(const float4*)src;
        uint2 h;
        h.x = h2pack(v.x * sc, v.y * sc);
        h.y = h2pack(v.z * sc, v.w * sc);
        *(uint2*)&g_Wh[k * 192 + c] = h;
    }
}

// ---------------------------------------------------------------------------
// QKV projection as an fp16 smem GEMM, cp.async staging only (R13 proven).
// ---------------------------------------------------------------------------
__global__ __launch_bounds__(256) void qkv_kernel()
{
    extern __shared__ __half smh[];
    __half* Xs = smh;               // [128][XSK]
    __half* Ws = smh + 128 * XSK;   // [128][WSK]

    const int tid  = threadIdx.x;
    const int row0 = blockIdx.x * 128;

    #pragma unroll
    for (int idx = tid; idx < 128 * 16; idx += 256) {
        int r = idx >> 4, c8 = (idx & 15) * 8;
        cpa16(&Xs[r * XSK + c8], g_Xh + (size_t)(row0 + r) * DM + c8);
    }
    #pragma unroll
    for (int idx = tid; idx < 128 * 24; idx += 256) {
        int k = idx / 24, c8 = (idx % 24) * 8;
        cpa16(&Ws[k * WSK + c8], g_Wh + k * 192 + c8);
    }
    CP_COMMIT();
    CP_WAIT0();
    __syncthreads();

    const int warp = tid >> 5, lane = tid & 31;
    const int g = lane >> 2, qi = lane & 3;
    const int rowbase = 32 * (warp >> 1);
    const int colbase = 96 * (warp & 1);
    const int arow  = ((lane >> 3) & 1) * 8 + (lane & 7);
    const int acol8 = (lane >> 4) * 8;
    const int wrow  = ((lane >> 3) & 1) * 8 + (lane & 7);
    const int wcol8 = (lane >> 4) * 8;

    float s[2][12][4];
    #pragma unroll
    for (int rg = 0; rg < 2; rg++)
        #pragma unroll
        for (int nt = 0; nt < 12; nt++)
            #pragma unroll
            for (int e = 0; e < 4; e++) s[rg][nt][e] = 0.f;

    #pragma unroll
    for (int ks = 0; ks < 8; ks++) {
        uint32_t qa0[4], qa1[4];
        ldm_x4(qa0, &Xs[(rowbase + arow) * XSK + 16 * ks + acol8]);
        ldm_x4(qa1, &Xs[(rowbase + 16 + arow) * XSK + 16 * ks + acol8]);
        #pragma unroll
        for (int np = 0; np < 6; np++) {
            uint32_t wf[4];
            ldm_x4t(wf, &Ws[(16 * ks + wrow) * WSK + colbase + 16 * np + wcol8]);
            mma_f16(s[0][2 * np],     qa0, wf[0], wf[1]);
            mma_f16(s[1][2 * np],     qa1, wf[0], wf[1]);
            mma_f16(s[0][2 * np + 1], qa0, wf[2], wf[3]);
            mma_f16(s[1][2 * np + 1], qa1, wf[2], wf[3]);
        }
    }

    #pragma unroll
    for (int rg = 0; rg < 2; rg++) {
        #pragma unroll
        for (int nt = 0; nt < 12; nt++) {
            int c0 = colbase + 8 * nt + 2 * qi;
            int rA = row0 + rowbase + 16 * rg + g;
            #pragma unroll
            for (int half = 0; half < 2; half++) {
                int r = rA + 8 * half;
                __half2 hv = __floats2half2_rn(s[rg][nt][2 * half + 0],
                                               s[rg][nt][2 * half + 1]);
                if (c0 < 64) {
                    *(__half2*)&g_Qh[(size_t)r * HD + c0] = hv;
                } else if (c0 < 128) {
                    *(__half2*)&g_Kh[(size_t)r * HD + (c0 - 64)] = hv;
                } else {
                    *(__half2*)&g_Vh[(size_t)r * HD + (c0 - 128)] = hv;
                }
            }
        }
    }
}

// ---------------------------------------------------------------------------
// Causal flash attention, split-KV with CH=16 chunks.
// Work units per batch: sum over qb of ceil((qb+1)/16) = 160; grid (160, NB).
// Mapping: group gI (qb in [16gI,16gI+15]) has gI+1 chunks;
// offsets[gI] = 8*gI*(gI+1). Inner loop identical to R11-R13 (proven).
// ---------------------------------------------------------------------------
__global__ __launch_bounds__(128, 4) void attn_kernel(float* __restrict__ Out)
{
    extern __shared__ float sm[];
    __half* base = (__half*)sm;
    __half* Kb[2] = { base,                base + 64 * HSK };
    __half* Vh[2] = { base + 2 * 64 * HSK, base + 3 * 64 * HSK };

    // map work unit -> (qb, chunk); biggest chunks scheduled first
    const int wu = 159 - (int)blockIdx.x;
    int gI = 0;
    while (wu >= 8 * (gI + 1) * (gI + 2)) gI++;       // offsets[g] = 8g(g+1)
    const int rem   = wu - 8 * gI * (gI + 1);
    const int qb    = 16 * gI + rem / (gI + 1);
    const int chunk = rem % (gI + 1);
    const int nch   = qb / CH + 1;
    const int t0 = chunk * CH;
    const int t1 = min(t0 + CH, qb + 1);

    const int b    = blockIdx.y;
    const int tid  = threadIdx.x;
    const int warp = tid >> 5, lane = tid & 31;
    const int g    = lane >> 2, qi = lane & 3;

    const int arow  = ((lane >> 3) & 1) * 8 + (lane & 7);
    const int acol8 = (lane >> 4) * 8;
    const int krow  = (lane & 7) + ((lane >> 4) << 3);
    const int kcol8 = ((lane >> 3) & 1) * 8;
    const int vrow  = ((lane >> 3) & 1) * 8 + (lane & 7);
    const int vcol8 = (lane >> 4) * 8;

    const __half* Kg0 = g_Kh + (size_t)b * TLEN * HD;
    const __half* Vg0 = g_Vh + (size_t)b * TLEN * HD;

    // preload K(t0)+V(t0) as one group
    #pragma unroll
    for (int idx = tid; idx < 64 * 8; idx += 128) {
        int r = idx >> 3, c8 = (idx & 7) * 8;
        cpa16(&Kb[0][r * HSK + c8], Kg0 + (size_t)(t0 * 64 + r) * HD + c8);
        cpa16(&Vh[0][r * HSK + c8], Vg0 + (size_t)(t0 * 64 + r) * HD + c8);
    }
    CP_COMMIT();

    // stage Q (fp16, pre-scaled) into Kb[1], pull A-fragments
    const __half* Qg = g_Qh + ((size_t)b * TLEN + (size_t)qb * 64) * HD;
    #pragma unroll
    for (int idx = tid; idx < 64 * 8; idx += 128) {
        int r = idx >> 3, c8 = (idx & 7) * 8;
        *(uint4*)&Kb[1][r * HSK + c8] = *(const uint4*)(Qg + (size_t)r * HD + c8);
    }
    __syncthreads();

    uint32_t qa[4][4];
    #pragma unroll
    for (int ks = 0; ks < 4; ks++)
        ldm_x4(qa[ks], &Kb[1][(16 * warp + arow) * HSK + 16 * ks + acol8]);

    float o[8][4];
    #pragma unroll
    for (int nt = 0; nt < 8; nt++)
        #pragma unroll
        for (int e = 0; e < 4; e++) o[nt][e] = 0.f;
    float m0 = -1e30f, m1 = -1e30f, l0 = 0.f, l1 = 0.f;  // l: lane-partial

    const int qr = 16 * warp + g;

    for (int kb = t0; kb < t1; kb++) {
        const int cur = (kb - t0) & 1;

        CP_WAIT0();          // K(kb), V(kb) landed
        __syncthreads();     // visible CTA-wide; prev readers of [1-cur] done

        // one prefetch group: K(kb+1) + V(kb+1) into [1-cur]
        if (kb + 1 < t1) {
            const __half* Kg = Kg0 + (size_t)(kb + 1) * 64 * HD;
            const __half* Vg = Vg0 + (size_t)(kb + 1) * 64 * HD;
            #pragma unroll
            for (int idx = tid; idx < 64 * 8; idx += 128) {
                int r = idx >> 3, c8 = (idx & 7) * 8;
                cpa16(&Kb[1 - cur][r * HSK + c8], Kg + (size_t)r * HD + c8);
                cpa16(&Vh[1 - cur][r * HSK + c8], Vg + (size_t)r * HD + c8);
            }
        }
        CP_COMMIT();

        // --- S = Q K^T (fp16, 4 k-steps of 16) ---
        float s[8][4];
        #pragma unroll
        for (int nt = 0; nt < 8; nt++)
            #pragma unroll
            for (int e = 0; e < 4; e++) s[nt][e] = 0.f;

        #pragma unroll
        for (int ks = 0; ks < 4; ks++) {
            #pragma unroll
            for (int ntp = 0; ntp < 4; ntp++) {
                uint32_t kf[4];
                ldm_x4(kf, &Kb[cur][(16 * ntp + krow) * HSK + 16 * ks + kcol8]);
                mma_f16(s[2 * ntp],     qa[ks], kf[0], kf[1]);
                mma_f16(s[2 * ntp + 1], qa[ks], kf[2], kf[3]);
            }
        }

        // --- causal mask: diagonal tile only ---
        if (kb == qb) {
            #pragma unroll
            for (int nt = 0; nt < 8; nt++) {
                int c0 = 8 * nt + 2 * qi;
                if (c0     > qr    ) s[nt][0] = -1e30f;
                if (c0 + 1 > qr    ) s[nt][1] = -1e30f;
                if (c0     > qr + 8) s[nt][2] = -1e30f;
                if (c0 + 1 > qr + 8) s[nt][3] = -1e30f;
            }
        }

        // --- online softmax (exp2 domain); l lane-partial ---
        float rm0 = -1e30f, rm1 = -1e30f;
        #pragma unroll
        for (int nt = 0; nt < 8; nt++) {
            rm0 = fmaxf(rm0, fmaxf(s[nt][0], s[nt][1]));
            rm1 = fmaxf(rm1, fmaxf(s[nt][2], s[nt][3]));
        }
        rm0 = fmaxf(rm0, __shfl_xor_sync(0xffffffffu, rm0, 1));
        rm0 = fmaxf(rm0, __shfl_xor_sync(0xffffffffu, rm0, 2));
        rm1 = fmaxf(rm1, __shfl_xor_sync(0xffffffffu, rm1, 1));
        rm1 = fmaxf(rm1, __shfl_xor_sync(0xffffffffu, rm1, 2));

        float mn0 = fmaxf(m0, rm0), mn1 = fmaxf(m1, rm1);
        float a0 = ex2f(m0 - mn0), a1 = ex2f(m1 - mn1);
        m0 = mn0; m1 = mn1;

        float rs0 = 0.f, rs1 = 0.f;
        #pragma unroll
        for (int nt = 0; nt < 8; nt++) {
            s[nt][0] = ex2f(s[nt][0] - mn0);
            s[nt][1] = ex2f(s[nt][1] - mn0);
            s[nt][2] = ex2f(s[nt][2] - mn1);
            s[nt][3] = ex2f(s[nt][3] - mn1);
            rs0 += s[nt][0] + s[nt][1];
            rs1 += s[nt][2] + s[nt][3];
        }
        l0 = l0 * a0 + rs0;
        l1 = l1 * a1 + rs1;

        #pragma unroll
        for (int nt = 0; nt < 8; nt++) {
            o[nt][0] *= a0; o[nt][1] *= a0;
            o[nt][2] *= a1; o[nt][3] *= a1;
        }

        // --- O += P V : P packed to fp16 A-frags in registers ---
        #pragma unroll
        for (int k4 = 0; k4 < 4; k4++) {
            uint32_t pa[4];
            pa[0] = h2pack(s[2 * k4][0],     s[2 * k4][1]);
            pa[1] = h2pack(s[2 * k4][2],     s[2 * k4][3]);
            pa[2] = h2pack(s[2 * k4 + 1][0], s[2 * k4 + 1][1]);
            pa[3] = h2pack(s[2 * k4 + 1][2], s[2 * k4 + 1][3]);
            #pragma unroll
            for (int np = 0; np < 4; np++) {
                uint32_t vf[4];
                ldm_x4t(vf, &Vh[cur][(16 * k4 + vrow) * HSK + 16 * np + vcol8]);
                mma_f16(o[2 * np],     pa, vf[0], vf[1]);
                mma_f16(o[2 * np + 1], pa, vf[2], vf[3]);
            }
        }
    }

    // --- epilogue: reduce lane-partial l across the 4 qi lanes (exact) ---
    l0 += __shfl_xor_sync(0xffffffffu, l0, 1);
    l0 += __shfl_xor_sync(0xffffffffu, l0, 2);
    l1 += __shfl_xor_sync(0xffffffffu, l1, 1);
    l1 += __shfl_xor_sync(0xffffffffu, l1, 2);

    if (nch == 1) {
        float* Og = Out + ((size_t)b * TLEN + (size_t)qb * 64) * HD;
        float i0 = 1.f / l0, i1 = 1.f / l1;
        #pragma unroll
        for (int nt = 0; nt < 8; nt++) {
            int c0 = 8 * nt + 2 * qi;
            *(float2*)&Og[(size_t)qr * HD + c0] =
                make_float2(o[nt][0] * i0, o[nt][1] * i0);
            *(float2*)&Og[(size_t)(qr + 8) * HD + c0] =
                make_float2(o[nt][2] * i1, o[nt][3] * i1);
        }
    } else {
        const size_t pi = ((size_t)(b * 64 + qb) * MAXNCH + chunk);
        float* Po = g_Po + pi * 64 * 64;
        #pragma unroll
        for (int nt = 0; nt < 8; nt++) {
            int c0 = 8 * nt + 2 * qi;
            *(float2*)&Po[(size_t)qr * 64 + c0] =
                make_float2(o[nt][0], o[nt][1]);
            *(float2*)&Po[(size_t)(qr + 8) * 64 + c0] =
                make_float2(o[nt][2], o[nt][3]);
        }
        if (qi == 0) {
            g_Pm[pi * 64 + qr]     = m0;
            g_Pl[pi * 64 + qr]     = l0;
            g_Pm[pi * 64 + qr + 8] = m1;
            g_Pl[pi * 64 + qr + 8] = l1;
        }
    }
}

// ---------------------------------------------------------------------------
// Combine partials for qb >= CH. Grid (64-CH, NB), 256 threads.
// ---------------------------------------------------------------------------
__global__ __launch_bounds__(256) void combine_kernel(float* __restrict__ Out)
{
    const int qb  = CH + (int)blockIdx.x;     // 16..63
    const int b   = blockIdx.y;
    const int nch = qb / CH + 1;              // 2..4
    const int tid = threadIdx.x;
    const int row = tid >> 2;
    const int c0  = (tid & 3) * 16;
    const size_t qt = (size_t)(b * 64 + qb);

    float mv[MAXNCH], lv[MAXNCH];
    float mmax = -1e30f;
    for (int c = 0; c < nch; c++) {
        mv[c] = g_Pm[(qt * MAXNCH + c) * 64 + row];
        lv[c] = g_Pl[(qt * MAXNCH + c) * 64 + row];
        mmax = fmaxf(mmax, mv[c]);
    }
    float denom = 0.f;
    float w[MAXNCH];
    for (int c = 0; c < nch; c++) {
        w[c] = ex2f(mv[c] - mmax);
        denom += w[c] * lv[c];
    }
    const float inv = 1.f / denom;

    float4 acc[4];
    #pragma unroll
    for (int j = 0; j < 4; j++) acc[j] = make_float4(0.f, 0.f, 0.f, 0.f);

    for (int c = 0; c < nch; c++) {
        const float4* src = (const float4*)(g_Po +
            ((qt * MAXNCH + c) * 64 + row) * 64 + c0);
        float wc = w[c];
        #pragma unroll
        for (int j = 0; j < 4; j++) {
            float4 v = src[j];
            acc[j].x += wc * v.x; acc[j].y += wc * v.y;
            acc[j].z += wc * v.z; acc[j].w += wc * v.w;
        }
    }

    float4* dst = (float4*)(Out + ((size_t)b * TLEN + (size_t)qb * 64 + row) * HD + c0);
    #pragma unroll
    for (int j = 0; j < 4; j++) {
        dst[j] = make_float4(acc[j].x * inv, acc[j].y * inv,
                             acc[j].z * inv, acc[j].w * inv);
    }
}

// ---------------------------------------------------------------------------
extern "C" void kernel_launch(void* const* d_in, const int* in_sizes, int n_in,
                              void* d_out, int out_size)
{
    const float* x  = (const float*)d_in[0];
    const float* Wq = (const float*)d_in[1];
    const float* Wk = (const float*)d_in[2];
    const float* Wv = (const float*)d_in[3];
    float* out = (float*)d_out;

    const int smem_qkv  = (128 * XSK + 128 * WSK) * (int)sizeof(__half); // 86016
    const int smem_attn = 4 * 64 * HSK * (int)sizeof(__half);            // 36864

    cudaFuncSetAttribute(qkv_kernel,
        cudaFuncAttributeMaxDynamicSharedMemorySize, smem_qkv);
    cudaFuncSetAttribute(attn_kernel,
        cudaFuncAttributeMaxDynamicSharedMemorySize, smem_attn);

    cvt_kernel<<<1184, 256>>>(x, Wq, Wk, Wv);
    qkv_kernel<<<BT / 128, 256, smem_qkv>>>();
    attn_kernel<<<dim3(160, NB), 128, smem_attn>>>(out);
    combine_kernel<<<dim3(64 - CH, NB), 256>>>(out);
}